// round 5
// baseline (speedup 1.0000x reference)
#include <cuda_runtime.h>
#include <math.h>

// Problem shape (fixed by the dataset)
#define NB   8
#define NC   128
#define NHW  1024
#define NTOT (NB*NHW)      // 8192
#define NCLS 5
#define INV_T 10.0f        // 1/TEMPERATURE, folded into student normalization

#define BM 128             // i-rows per block
#define BN 128             // j-cols per tile
#define KD 128

// ---------------- device scratch (no allocations allowed) ----------------
__device__ float g_s[NTOT*NC];        // student, L2-normalized * (1/T), [N][C]
__device__ float g_t[NTOT*NC];        // teacher, L2-normalized,         [N][C]
__device__ float g_sep[2*NTOT];       // partial sum-of-exp per (half, i); each slot single-writer
__device__ float g_clsum[NCLS*NC];    // per-class sums of teacher rows
__device__ float g_clcnt[NCLS];
__device__ float g_acc[2];            // {sum w*mlpp, sum w}
__device__ int   g_lmode;             // 0 = int32 labels, 1 = int64 labels

// ---------------- helpers ----------------
__device__ __forceinline__ unsigned long long fma2(unsigned long long a,
                                                   unsigned long long b,
                                                   unsigned long long c) {
    unsigned long long d;
    asm("fma.rn.f32x2 %0, %1, %2, %3;" : "=l"(d) : "l"(a), "l"(b), "l"(c));
    return d;
}
__device__ __forceinline__ void cpasync16(unsigned smem, const void* g) {
    asm volatile("cp.async.cg.shared.global [%0], [%1], 16;\n" :: "r"(smem), "l"(g));
}
__device__ __forceinline__ void cpcommit() {
    asm volatile("cp.async.commit_group;\n" ::: "memory");
}
template<int N> __device__ __forceinline__ void cpwait() {
    asm volatile("cp.async.wait_group %0;\n" :: "n"(N) : "memory");
}
__device__ __forceinline__ int get_label(const void* p, int i) {
    if (g_lmode) return (int)(((const long long*)p)[i]);
    return ((const int*)p)[i];
}
// swizzle: chunk slot within a 32-chunk row
__device__ __forceinline__ int swz(int row) { return (row ^ (row >> 3)) & 7; }

// ---------------- K0: label dtype probe ----------------
__global__ void k_detect(const int* sl, const int* tl) {
    if (threadIdx.x == 0) {
        int allzero = 1;
        for (int i = 1; i < 256; i += 2) {
            if (sl[i] != 0 || tl[i] != 0) { allzero = 0; break; }
        }
        g_lmode = allzero;  // int64 storage -> every odd 32-bit word is a zero high-word
    }
}

// ---------------- K1: zero accumulators ----------------
__global__ void k_zero() {
    int t = threadIdx.x;
    if (t < NCLS*NC) g_clsum[t] = 0.f;
    if (t < NCLS)    g_clcnt[t] = 0.f;
    if (t < 2)       g_acc[t]   = 0.f;
}

// ---------------- K2: normalize + transpose ([B,C,HW] -> [N,C]) ----------------
// grid (256, 2): y==0 student (scale 1/T), y==1 teacher. block 256 = 32hw x 8c.
__global__ __launch_bounds__(256) void k_norm(const float* __restrict__ s_in,
                                              const float* __restrict__ t_in) {
    __shared__ float sh[NC][33];
    __shared__ float part[8][32];
    __shared__ float invn[32];
    const float* in  = (blockIdx.y == 0) ? s_in : t_in;
    float*       out = (blockIdx.y == 0) ? g_s  : g_t;
    const float  scale = (blockIdx.y == 0) ? INV_T : 1.0f;
    int b   = blockIdx.x >> 5;
    int hw0 = (blockIdx.x & 31) << 5;
    int tx = threadIdx.x & 31, ty = threadIdx.x >> 5;
    float p = 0.f;
    const float* base = in + (size_t)b * NC * NHW + hw0 + tx;
    for (int c = ty; c < NC; c += 8) {
        float v = base[(size_t)c * NHW];
        sh[c][tx] = v;
        p += v * v;
    }
    part[ty][tx] = p;
    __syncthreads();
    if (ty == 0) {
        float s = 0.f;
        #pragma unroll
        for (int q = 0; q < 8; q++) s += part[q][tx];
        invn[tx] = rsqrtf(s) * scale;
    }
    __syncthreads();
    int n0 = b * NHW + hw0;
    for (int idx = threadIdx.x; idx < NC * 32; idx += 256) {
        int c = idx & 127, q = idx >> 7;
        out[(size_t)(n0 + q) * NC + c] = sh[c][q] * invn[q];
    }
}

// ---------------- K3: per-class teacher sums + counts ----------------
__global__ __launch_bounds__(128) void k_clsum(const void* tl) {
    __shared__ float acc[NCLS][NC];
    __shared__ float cnt[NCLS];
    int tid = threadIdx.x;
    for (int q = tid; q < NCLS*NC; q += 128) ((float*)acc)[q] = 0.f;
    if (tid < NCLS) cnt[tid] = 0.f;
    __syncthreads();
    int base = blockIdx.x * 128;
    for (int r = 0; r < 128; r++) {
        int row = base + r;
        int lbl = get_label(tl, row);
        lbl = min(max(lbl, 0), NCLS - 1);
        acc[lbl][tid] += g_t[(size_t)row * NC + tid];
        if (tid == 0) cnt[lbl] += 1.f;
    }
    __syncthreads();
    for (int q = tid; q < NCLS*NC; q += 128) atomicAdd(&g_clsum[q], ((float*)acc)[q]);
    if (tid < NCLS) atomicAdd(&g_clcnt[tid], cnt[tid]);
}

// ---------------- K4: fused GEMM + exp + row-sum -> partial sum-of-exp ----------------
// grid = 128 blocks: block b handles i-tile (b>>1) x j-half (b&1).
// SMEM layout per tile: row-major [row][32 chunks of 16B], chunk slot swizzled:
//   slot(row,k4) = k4 ^ ((row ^ (row>>3)) & 7)
// -> cp.async stores conflict-free (1 row / warp, all 32 chunk cols);
//    a-reads (rows 8ty+r, 2 rows/warp differing by 8): distinct banks + broadcast -> 1 phase;
//    b-reads (cols 16c+tx, 16 consecutive rows/warp): 8 bank groups x 2-way -> 2 phases (min).
// 8x8 per-thread tile, f32x2 accumulators paired along k.
extern __shared__ float smem3[];

__global__ __launch_bounds__(256, 1) void k_main() {
    float* sA  = smem3;                  // 16384 floats (64KB)
    float* tB0 = smem3 + BM * KD;        // 16384
    float* tB1 = smem3 + 2 * BM * KD;    // 16384
    int tid = threadIdx.x;
    int tx = tid & 15, ty = tid >> 4;
    int i0    = (blockIdx.x >> 1) * BM;
    int half  = blockIdx.x & 1;
    int jbase = half * (NTOT / 2);
    unsigned sA_u  = (unsigned)__cvta_generic_to_shared(sA);
    unsigned tB_u0 = (unsigned)__cvta_generic_to_shared(tB0);
    unsigned tB_u1 = (unsigned)__cvta_generic_to_shared(tB1);

    // prologue: sA (student tile, reused for all j) + teacher tile 0 -> one group
    #pragma unroll
    for (int it = 0; it < 16; it++) {
        int idx = tid + it * 256;
        int row = idx >> 5, k4 = idx & 31;
        int slot = row * 32 + (k4 ^ swz(row));
        cpasync16(sA_u + slot * 16, g_s + (size_t)(i0 + row) * KD + k4 * 4);
    }
    #pragma unroll
    for (int it = 0; it < 16; it++) {
        int idx = tid + it * 256;
        int col = idx >> 5, k4 = idx & 31;
        int slot = col * 32 + (k4 ^ swz(col));
        cpasync16(tB_u0 + slot * 16, g_t + (size_t)(jbase + col) * KD + k4 * 4);
    }
    cpcommit();

    // per-thread row/col swizzle constants
    int swa[8], swb[8];
    #pragma unroll
    for (int r = 0; r < 8; r++) swa[r] = swz(8 * ty + r);
    #pragma unroll
    for (int c = 0; c < 8; c++) swb[c] = swz(16 * c + tx);

    float rs[8];
    #pragma unroll
    for (int r = 0; r < 8; r++) rs[r] = 0.f;

    const int NT = (NTOT / 2) / BN;  // 32 tiles
    for (int jt = 0; jt < NT; jt++) {
        if (jt + 1 < NT) {
            int j0 = jbase + (jt + 1) * BN;
            unsigned dstb = ((jt + 1) & 1) ? tB_u1 : tB_u0;
            #pragma unroll
            for (int it = 0; it < 16; it++) {
                int idx = tid + it * 256;
                int col = idx >> 5, k4 = idx & 31;
                int slot = col * 32 + (k4 ^ swz(col));
                cpasync16(dstb + slot * 16, g_t + (size_t)(j0 + col) * KD + k4 * 4);
            }
            cpcommit();
            cpwait<1>();   // current tile's group complete; next tile in flight
        } else {
            cpwait<0>();
        }
        __syncthreads();

        const float* tb = (jt & 1) ? tB1 : tB0;
        unsigned long long acc[8][8];
        #pragma unroll
        for (int r = 0; r < 8; r++)
            #pragma unroll
            for (int c = 0; c < 8; c++) acc[r][c] = 0ull;

        #pragma unroll 4
        for (int k4 = 0; k4 < 32; k4++) {
            ulonglong2 a2[8], b2[8];
            #pragma unroll
            for (int r = 0; r < 8; r++)
                a2[r] = *(const ulonglong2*)(sA + (size_t)((8 * ty + r) * 32 + (k4 ^ swa[r])) * 4);
            #pragma unroll
            for (int c = 0; c < 8; c++)
                b2[c] = *(const ulonglong2*)(tb + (size_t)((16 * c + tx) * 32 + (k4 ^ swb[c])) * 4);
            #pragma unroll
            for (int r = 0; r < 8; r++)
                #pragma unroll
                for (int c = 0; c < 8; c++) {
                    acc[r][c] = fma2(a2[r].x, b2[c].x, acc[r][c]);
                    acc[r][c] = fma2(a2[r].y, b2[c].y, acc[r][c]);
                }
        }
        // exp + row accumulate (|logit| <= 10 -> no max pass needed, fp32 safe)
        #pragma unroll
        for (int r = 0; r < 8; r++) {
            float e = 0.f;
            #pragma unroll
            for (int c = 0; c < 8; c++) {
                unsigned long long v = acc[r][c];
                float lo = __uint_as_float((unsigned)v);
                float hi = __uint_as_float((unsigned)(v >> 32));
                e += __expf(lo + hi);
            }
            rs[r] += e;
        }
        __syncthreads();   // protects buffer reuse for next iteration's cp.async
    }

    // reduce 16 tx-partials per row (alias sA; safe after final barrier above)
    float* red = sA;  // 128 x 17
    #pragma unroll
    for (int r = 0; r < 8; r++) red[(8 * ty + r) * 17 + tx] = rs[r];
    __syncthreads();
    if (tid < BM) {
        float s = 0.f;
        #pragma unroll
        for (int x = 0; x < 16; x++) s += red[tid * 17 + x];
        g_sep[half * NTOT + i0 + tid] = s;   // single writer per slot: deterministic
    }
}

// ---------------- K5: per-anchor terms + reduction ----------------
__global__ __launch_bounds__(256) void k_final(const void* sl) {
    int i = blockIdx.x * 256 + threadIdx.x;
    int lbl = get_label(sl, i);
    int lc = min(max(lbl, 0), NCLS - 1);
    float cnt = g_clcnt[lc];
    float lse = logf(g_sep[i] + g_sep[NTOT + i]);
    const float4* sv = (const float4*)(g_s + (size_t)i * NC);
    const float4* cv = (const float4*)(g_clsum + lc * NC);
    float dot = 0.f;   // = sum_{j: tl_j == lbl} logit(i,j)   (1/T already folded into g_s)
    #pragma unroll
    for (int q = 0; q < 32; q++) {
        float4 a = sv[q], b = cv[q];
        dot += a.x * b.x + a.y * b.y + a.z * b.z + a.w * b.w;
    }
    float mlpp = (dot - cnt * lse) / (cnt + 1e-8f);
    float w = (cnt > 1e-8f && lbl != 0) ? 1.f : 0.f;

    __shared__ float r1[256], r2[256];
    r1[threadIdx.x] = w * mlpp;
    r2[threadIdx.x] = w;
    __syncthreads();
    for (int s = 128; s > 0; s >>= 1) {
        if (threadIdx.x < s) {
            r1[threadIdx.x] += r1[threadIdx.x + s];
            r2[threadIdx.x] += r2[threadIdx.x + s];
        }
        __syncthreads();
    }
    if (threadIdx.x == 0) {
        atomicAdd(&g_acc[0], r1[0]);
        atomicAdd(&g_acc[1], r2[0]);
    }
}

__global__ void k_loss(float* out) {
    out[0] = -g_acc[0] / g_acc[1];
}

// ---------------- launch ----------------
extern "C" void kernel_launch(void* const* d_in, const int* in_sizes, int n_in,
                              void* d_out, int out_size) {
    const float* s_in = (const float*)d_in[0];
    const float* t_in = (const float*)d_in[1];
    const void*  sl   = d_in[2];
    const void*  tl   = d_in[3];
    float* out = (float*)d_out;

    cudaFuncSetAttribute(k_main, cudaFuncAttributeMaxDynamicSharedMemorySize,
                         3 * BM * KD * (int)sizeof(float));

    k_detect<<<1, 32>>>((const int*)sl, (const int*)tl);
    k_zero<<<1, 640>>>();
    k_norm<<<dim3(256, 2), 256>>>(s_in, t_in);
    k_clsum<<<NTOT / 128, 128>>>(tl);
    k_main<<<(NTOT / BM) * 2, 256, 3 * BM * KD * sizeof(float)>>>();
    k_final<<<NTOT / 256, 256>>>(sl);
    k_loss<<<1, 1>>>(out);
}

// round 8
// speedup vs baseline: 3.0564x; 3.0564x over previous
#include <cuda_runtime.h>
#include <cuda_bf16.h>
#include <math.h>

// Problem shape (fixed by dataset)
#define NB   8
#define NC   128
#define NHW  1024
#define NTOT (NB*NHW)      // 8192
#define NCLS 5
#define INV_T 10.0f        // 1/TEMPERATURE folded into student normalization

#define BM 128             // i-rows per block
#define BN 128             // j-cols per tile
#define NT 32              // j-tiles per block (each block covers half the j range)

// dynamic smem layout (bytes): A(hi,lo) resident + B double-buffered (hi,lo)
#define SM_A   0           // Ahi 32768 | Alo 32768
#define SM_B0  65536       // B0hi 32768 | B0lo 32768
#define SM_B1  131072      // B1hi 32768 | B1lo 32768
#define SMEM_TOTAL 196608

// ---------------- device scratch (no allocations allowed) ----------------
__device__ float g_s[NTOT*NC];            // student fp32, *1/T (k_final dot)
__device__ float g_t[NTOT*NC];            // teacher fp32 (k_clsum)
__device__ __nv_bfloat16 g_sh[NTOT*NC], g_sl[NTOT*NC];   // student hi/lo bf16 (*1/T)
__device__ __nv_bfloat16 g_th[NTOT*NC], g_tl[NTOT*NC];   // teacher hi/lo bf16
__device__ float g_sep[2*NTOT];           // partial sum-of-exp (half, i); single writer
__device__ float g_clsum[NCLS*NC];
__device__ float g_clcnt[NCLS];
__device__ float g_acc[2];
__device__ int   g_lmode;

// ---------------- helpers ----------------
__device__ __forceinline__ void cpasync16(unsigned smem, const void* g) {
    asm volatile("cp.async.cg.shared.global [%0], [%1], 16;\n" :: "r"(smem), "l"(g));
}
__device__ __forceinline__ void cpcommit() {
    asm volatile("cp.async.commit_group;\n" ::: "memory");
}
template<int N> __device__ __forceinline__ void cpwait() {
    asm volatile("cp.async.wait_group %0;\n" :: "n"(N) : "memory");
}
__device__ __forceinline__ int get_label(const void* p, int i) {
    if (g_lmode) return (int)(((const long long*)p)[i]);
    return ((const int*)p)[i];
}
__device__ __forceinline__ void ldsm4(unsigned* r, unsigned addr) {
    asm volatile("ldmatrix.sync.aligned.m8n8.x4.shared.b16 {%0,%1,%2,%3}, [%4];"
                 : "=r"(r[0]), "=r"(r[1]), "=r"(r[2]), "=r"(r[3]) : "r"(addr));
}
__device__ __forceinline__ void mma16816(float* c, const unsigned* a, unsigned b0, unsigned b1) {
    asm volatile("mma.sync.aligned.m16n8k16.row.col.f32.bf16.bf16.f32 "
                 "{%0,%1,%2,%3}, {%4,%5,%6,%7}, {%8,%9}, {%0,%1,%2,%3};"
                 : "+f"(c[0]), "+f"(c[1]), "+f"(c[2]), "+f"(c[3])
                 : "r"(a[0]), "r"(a[1]), "r"(a[2]), "r"(a[3]), "r"(b0), "r"(b1));
}

// Load one 128x128 bf16 tile (row-major [row][128]) into SMEM.
// Row = 256B = 16 chunks of 16B; chunk swizzle c' = c ^ (row & 7):
// 8 consecutive rows at a fixed chunk hit 8 distinct bank groups (ldmatrix conflict-free).
__device__ __forceinline__ void load_tile(unsigned dst, const __nv_bfloat16* src, int tid) {
    #pragma unroll
    for (int it = 0; it < 8; it++) {
        int idx = tid + it * 256;
        int row = idx >> 4, c = idx & 15;
        unsigned off = (unsigned)(row * 256 + ((c ^ (row & 7)) << 4));
        cpasync16(dst + off, (const char*)src + row * 256 + c * 16);
    }
}

// ---------------- K0: label dtype probe ----------------
__global__ void k_detect(const int* sl, const int* tl) {
    if (threadIdx.x == 0) {
        int allzero = 1;
        for (int i = 1; i < 256; i += 2)
            if (sl[i] != 0 || tl[i] != 0) { allzero = 0; break; }
        g_lmode = allzero;   // int64 labels 0..4 -> all odd 32-bit words zero
    }
}

// ---------------- K1: zero accumulators ----------------
__global__ void k_zero() {
    int t = threadIdx.x;
    if (t < NCLS*NC) g_clsum[t] = 0.f;
    if (t < NCLS)    g_clcnt[t] = 0.f;
    if (t < 2)       g_acc[t]   = 0.f;
}

// ---------------- K2: normalize + transpose + bf16 hi/lo split ----------------
__global__ __launch_bounds__(256) void k_norm(const float* __restrict__ s_in,
                                              const float* __restrict__ t_in) {
    __shared__ float sh[NC][33];
    __shared__ float part[8][32];
    __shared__ float invn[32];
    int stu = (blockIdx.y == 0);
    const float* in   = stu ? s_in : t_in;
    float*       outf = stu ? g_s : g_t;
    __nv_bfloat16* outh = stu ? g_sh : g_th;
    __nv_bfloat16* outl = stu ? g_sl : g_tl;
    const float scale = stu ? INV_T : 1.0f;
    int b   = blockIdx.x >> 5;
    int hw0 = (blockIdx.x & 31) << 5;
    int tx = threadIdx.x & 31, ty = threadIdx.x >> 5;
    float p = 0.f;
    const float* base = in + (size_t)b * NC * NHW + hw0 + tx;
    for (int c = ty; c < NC; c += 8) {
        float v = base[(size_t)c * NHW];
        sh[c][tx] = v;
        p += v * v;
    }
    part[ty][tx] = p;
    __syncthreads();
    if (ty == 0) {
        float s = 0.f;
        #pragma unroll
        for (int q = 0; q < 8; q++) s += part[q][tx];
        invn[tx] = rsqrtf(s) * scale;
    }
    __syncthreads();
    int n0 = b * NHW + hw0;
    for (int idx = threadIdx.x; idx < NC * 32; idx += 256) {
        int c = idx & 127, q = idx >> 7;
        float v = sh[c][q] * invn[q];
        size_t o = (size_t)(n0 + q) * NC + c;
        outf[o] = v;
        __nv_bfloat16 h = __float2bfloat16(v);
        outh[o] = h;
        outl[o] = __float2bfloat16(v - __bfloat162float(h));
    }
}

// ---------------- K3: per-class teacher sums + counts ----------------
__global__ __launch_bounds__(256) void k_clsum(const void* tl) {
    int c = threadIdx.x & 127, h = threadIdx.x >> 7;
    int base = blockIdx.x * 64 + h * 32;
    float a0=0,a1=0,a2=0,a3=0,a4=0;
    int n0=0,n1=0,n2=0,n3=0,n4=0;
    #pragma unroll 4
    for (int r = 0; r < 32; r++) {
        int row = base + r;
        int lbl = get_label(tl, row);
        lbl = min(max(lbl, 0), NCLS - 1);
        float v = g_t[(size_t)row * NC + c];
        a0 += (lbl==0)?v:0.f; a1 += (lbl==1)?v:0.f; a2 += (lbl==2)?v:0.f;
        a3 += (lbl==3)?v:0.f; a4 += (lbl==4)?v:0.f;
        if (c == 0) { n0+=(lbl==0); n1+=(lbl==1); n2+=(lbl==2); n3+=(lbl==3); n4+=(lbl==4); }
    }
    atomicAdd(&g_clsum[0*NC+c], a0); atomicAdd(&g_clsum[1*NC+c], a1);
    atomicAdd(&g_clsum[2*NC+c], a2); atomicAdd(&g_clsum[3*NC+c], a3);
    atomicAdd(&g_clsum[4*NC+c], a4);
    if (c == 0) {
        atomicAdd(&g_clcnt[0], (float)n0); atomicAdd(&g_clcnt[1], (float)n1);
        atomicAdd(&g_clcnt[2], (float)n2); atomicAdd(&g_clcnt[3], (float)n3);
        atomicAdd(&g_clcnt[4], (float)n4);
    }
}

// ---------------- K4: warp-MMA bf16 split GEMM + exp + row-sum ----------------
// grid = 128 blocks: block b -> i-tile (b>>1), j-half (b&1). One wave on 148 SMs.
// Per j-tile: D[128,128] = S_hi T_hi^T + S_hi T_lo^T + S_lo T_hi^T (fp32 accum).
// 8 warps as 2(m) x 4(n): warp tile 64x32 -> 4 m-frags x 4 n-frags of m16n8k16.
extern __shared__ char smem_raw[];

__global__ __launch_bounds__(256, 1) void k_main() {
    unsigned sbase = (unsigned)__cvta_generic_to_shared(smem_raw);
    int tid = threadIdx.x, lane = tid & 31, wid = tid >> 5;
    int i0    = (blockIdx.x >> 1) * BM;
    int jhalf = blockIdx.x & 1;
    int jbase = jhalf * (NTOT / 2);
    int wr = wid & 1, wc = wid >> 1;
    int m_base = wr * 64, n_base = wc * 32;
    int sub = lane >> 3, l7 = lane & 7;

    // ldmatrix per-lane address bases.
    // A x4: lanes 0-7 rows+0-7 @chunk 2ks | 8-15 rows+8-15 @2ks | 16-23 rows+0-7 @2ks+1 | 24-31 rows+8-15 @2ks+1
    unsigned a_rel[4]; int a_sw[4];
    #pragma unroll
    for (int mf = 0; mf < 4; mf++) {
        int row = m_base + mf * 16 + (sub & 1) * 8 + l7;
        a_rel[mf] = row * 256; a_sw[mf] = row & 7;
    }
    const int a_co = sub >> 1;
    // B x4: lanes 0-7 rows+0-7 @2ks | 8-15 rows+0-7 @2ks+1 | 16-23 rows+8-15 @2ks | 24-31 rows+8-15 @2ks+1
    unsigned b_rel[2]; int b_sw[2];
    #pragma unroll
    for (int p = 0; p < 2; p++) {
        int row = n_base + p * 16 + (sub >> 1) * 8 + l7;
        b_rel[p] = row * 256; b_sw[p] = row & 7;
    }
    const int b_co = sub & 1;

    // prologue: A(hi,lo) resident + B tile 0 (hi,lo), one cp.async group
    load_tile(sbase + SM_A,         g_sh + (size_t)i0 * NC, tid);
    load_tile(sbase + SM_A + 32768, g_sl + (size_t)i0 * NC, tid);
    load_tile(sbase + SM_B0,         g_th + (size_t)jbase * NC, tid);
    load_tile(sbase + SM_B0 + 32768, g_tl + (size_t)jbase * NC, tid);
    cpcommit();

    float rs[8];
    #pragma unroll
    for (int q = 0; q < 8; q++) rs[q] = 0.f;

    for (int jt = 0; jt < NT; jt++) {
        int b = jt & 1;
        cpwait<0>();
        __syncthreads();   // B(jt) visible to all; all warps done reading buf b^1

        if (jt + 1 < NT) { // prefetch B(jt+1) into the other buffer
            int j0 = jbase + (jt + 1) * BN;
            unsigned dst = sbase + ((b ^ 1) ? SM_B1 : SM_B0);
            load_tile(dst,         g_th + (size_t)j0 * NC, tid);
            load_tile(dst + 32768, g_tl + (size_t)j0 * NC, tid);
            cpcommit();
        }

        unsigned Bh = sbase + (b ? SM_B1 : SM_B0);
        float c[4][4][4];
        #pragma unroll
        for (int mf = 0; mf < 4; mf++)
            #pragma unroll
            for (int nf = 0; nf < 4; nf++)
                #pragma unroll
                for (int q = 0; q < 4; q++) c[mf][nf][q] = 0.f;

        #pragma unroll 1
        for (int term = 0; term < 3; term++) {
            unsigned Ab = sbase + SM_A + ((term == 2) ? 32768u : 0u);
            unsigned Bb = Bh + ((term == 1) ? 32768u : 0u);
            #pragma unroll
            for (int ks = 0; ks < 8; ks++) {
                unsigned a[4][4], bf[2][4];
                #pragma unroll
                for (int mf = 0; mf < 4; mf++)
                    ldsm4(a[mf], Ab + a_rel[mf] + (((2*ks + a_co) ^ a_sw[mf]) << 4));
                #pragma unroll
                for (int p = 0; p < 2; p++)
                    ldsm4(bf[p], Bb + b_rel[p] + (((2*ks + b_co) ^ b_sw[p]) << 4));
                #pragma unroll
                for (int mf = 0; mf < 4; mf++) {
                    mma16816(c[mf][0], a[mf], bf[0][0], bf[0][1]);
                    mma16816(c[mf][1], a[mf], bf[0][2], bf[0][3]);
                    mma16816(c[mf][2], a[mf], bf[1][0], bf[1][1]);
                    mma16816(c[mf][3], a[mf], bf[1][2], bf[1][3]);
                }
            }
        }
        // exp + row accumulate (|logit| <= 10, fp32 exp safe; no max pass needed)
        #pragma unroll
        for (int mf = 0; mf < 4; mf++) {
            float e0 = 0.f, e1 = 0.f;
            #pragma unroll
            for (int nf = 0; nf < 4; nf++) {
                e0 += __expf(c[mf][nf][0]) + __expf(c[mf][nf][1]);
                e1 += __expf(c[mf][nf][2]) + __expf(c[mf][nf][3]);
            }
            rs[mf*2]   += e0;   // row = m_base + mf*16 + lane/4
            rs[mf*2+1] += e1;   // row = m_base + mf*16 + lane/4 + 8
        }
    }

    __syncthreads();                      // all reads of SMEM done -> reuse as reduce space
    float* red = (float*)smem_raw;        // [128][4] (per warp-column partials)
    #pragma unroll
    for (int q = 0; q < 8; q++) {
        rs[q] += __shfl_xor_sync(0xFFFFFFFFu, rs[q], 1);
        rs[q] += __shfl_xor_sync(0xFFFFFFFFu, rs[q], 2);
    }
    if ((lane & 3) == 0) {
        int r0 = m_base + (lane >> 2);
        #pragma unroll
        for (int mf = 0; mf < 4; mf++) {
            red[(r0 + mf*16    ) * 4 + wc] = rs[mf*2];
            red[(r0 + mf*16 + 8) * 4 + wc] = rs[mf*2+1];
        }
    }
    __syncthreads();
    if (tid < BM) {
        float s = red[tid*4] + red[tid*4+1] + red[tid*4+2] + red[tid*4+3];
        g_sep[jhalf * NTOT + i0 + tid] = s;   // single writer: deterministic
    }
}

// ---------------- K5: per-anchor terms + reduction ----------------
__global__ __launch_bounds__(256) void k_final(const void* sl) {
    int i = blockIdx.x * 256 + threadIdx.x;
    int lbl = get_label(sl, i);
    int lc = min(max(lbl, 0), NCLS - 1);
    float cnt = g_clcnt[lc];
    float lse = logf(g_sep[i] + g_sep[NTOT + i]);
    const float4* sv = (const float4*)(g_s + (size_t)i * NC);
    const float4* cv = (const float4*)(g_clsum + lc * NC);
    float dot = 0.f;   // = sum_{j: tl_j == lbl} logit(i,j)  (1/T folded into g_s)
    #pragma unroll
    for (int q = 0; q < 32; q++) {
        float4 a = sv[q], b = cv[q];
        dot += a.x * b.x + a.y * b.y + a.z * b.z + a.w * b.w;
    }
    float mlpp = (dot - cnt * lse) / (cnt + 1e-8f);
    float w = (cnt > 1e-8f && lbl != 0) ? 1.f : 0.f;

    __shared__ float r1[256], r2[256];
    r1[threadIdx.x] = w * mlpp;
    r2[threadIdx.x] = w;
    __syncthreads();
    for (int s = 128; s > 0; s >>= 1) {
        if (threadIdx.x < s) {
            r1[threadIdx.x] += r1[threadIdx.x + s];
            r2[threadIdx.x] += r2[threadIdx.x + s];
        }
        __syncthreads();
    }
    if (threadIdx.x == 0) {
        atomicAdd(&g_acc[0], r1[0]);
        atomicAdd(&g_acc[1], r2[0]);
    }
}

__global__ void k_loss(float* out) {
    out[0] = -g_acc[0] / g_acc[1];
}

// ---------------- launch ----------------
extern "C" void kernel_launch(void* const* d_in, const int* in_sizes, int n_in,
                              void* d_out, int out_size) {
    const float* s_in = (const float*)d_in[0];
    const float* t_in = (const float*)d_in[1];
    const void*  sl   = d_in[2];
    const void*  tl   = d_in[3];
    float* out = (float*)d_out;

    cudaFuncSetAttribute(k_main, cudaFuncAttributeMaxDynamicSharedMemorySize, SMEM_TOTAL);

    k_detect<<<1, 32>>>((const int*)sl, (const int*)tl);
    k_zero<<<1, 640>>>();
    k_norm<<<dim3(256, 2), 256>>>(s_in, t_in);
    k_clsum<<<NTOT / 64, 256>>>(tl);
    k_main<<<(NTOT / BM) * 2, 256, SMEM_TOTAL>>>();
    k_final<<<NTOT / 256, 256>>>(sl);
    k_loss<<<1, 1>>>(out);
}

// round 9
// speedup vs baseline: 3.4106x; 1.1159x over previous
#include <cuda_runtime.h>
#include <cuda_bf16.h>
#include <math.h>

// Problem shape (fixed by dataset)
#define NB   8
#define NC   128
#define NHW  1024
#define NTOT (NB*NHW)      // 8192
#define NCLS 5
// student scale = (1/T) * log2(e): lets epilogue use bare ex2.approx
#define S_SCALE (10.0f * 1.4426950408889634f)
#define LN2 0.6931471805599453f

#define BM 128             // i-rows per block
#define BN 128             // j-cols per tile
#define NT 32              // j-tiles per block (each block covers half the j range)

// dynamic smem layout (bytes): A(hi,lo) resident + B double-buffered (hi,lo)
#define SM_A   0           // Ahi 32768 | Alo 32768
#define SM_B0  65536       // B0hi 32768 | B0lo 32768
#define SM_B1  131072      // B1hi 32768 | B1lo 32768
#define SMEM_TOTAL 196608

// ---------------- device scratch (no allocations allowed) ----------------
__device__ float g_s[NTOT*NC];            // student fp32, *S_SCALE (k_final dot)
__device__ __nv_bfloat16 g_sh[NTOT*NC], g_sl[NTOT*NC];   // student hi/lo bf16 (*S_SCALE)
__device__ __nv_bfloat16 g_th[NTOT*NC], g_tl[NTOT*NC];   // teacher hi/lo bf16
__device__ float g_sep[2*NTOT];           // partial sum-of-exp (half, i); single writer
__device__ float g_clsum[NCLS*NC];
__device__ float g_clcnt[NCLS];
__device__ float g_acc[2];
__device__ int   g_done;
__device__ int   g_lmode;

// ---------------- helpers ----------------
__device__ __forceinline__ void cpasync16(unsigned smem, const void* g) {
    asm volatile("cp.async.cg.shared.global [%0], [%1], 16;\n" :: "r"(smem), "l"(g));
}
__device__ __forceinline__ void cpcommit() {
    asm volatile("cp.async.commit_group;\n" ::: "memory");
}
template<int N> __device__ __forceinline__ void cpwait() {
    asm volatile("cp.async.wait_group %0;\n" :: "n"(N) : "memory");
}
__device__ __forceinline__ int get_label(const void* p, int i) {
    if (g_lmode) return (int)(((const long long*)p)[i]);
    return ((const int*)p)[i];
}
__device__ __forceinline__ void ldsm4(unsigned* r, unsigned addr) {
    asm volatile("ldmatrix.sync.aligned.m8n8.x4.shared.b16 {%0,%1,%2,%3}, [%4];"
                 : "=r"(r[0]), "=r"(r[1]), "=r"(r[2]), "=r"(r[3]) : "r"(addr));
}
__device__ __forceinline__ void mma16816(float* c, const unsigned* a, unsigned b0, unsigned b1) {
    asm volatile("mma.sync.aligned.m16n8k16.row.col.f32.bf16.bf16.f32 "
                 "{%0,%1,%2,%3}, {%4,%5,%6,%7}, {%8,%9}, {%0,%1,%2,%3};"
                 : "+f"(c[0]), "+f"(c[1]), "+f"(c[2]), "+f"(c[3])
                 : "r"(a[0]), "r"(a[1]), "r"(a[2]), "r"(a[3]), "r"(b0), "r"(b1));
}
__device__ __forceinline__ float ex2f(float x) {
    float y; asm("ex2.approx.f32 %0, %1;" : "=f"(y) : "f"(x)); return y;
}

// Load one 128x128 bf16 tile (row-major [row][128]) into SMEM.
// Row = 256B = 16 chunks of 16B; chunk swizzle c' = c ^ (row & 7):
// 8 consecutive rows at a fixed chunk hit 8 distinct bank groups (ldmatrix conflict-free).
__device__ __forceinline__ void load_tile(unsigned dst, const __nv_bfloat16* src, int tid) {
    #pragma unroll
    for (int it = 0; it < 8; it++) {
        int idx = tid + it * 256;
        int row = idx >> 4, c = idx & 15;
        unsigned off = (unsigned)(row * 256 + ((c ^ (row & 7)) << 4));
        cpasync16(dst + off, (const char*)src + row * 256 + c * 16);
    }
}

// ---------------- K0: label dtype probe + zero accumulators ----------------
__global__ void k_init(const int* sl, const int* tl) {
    int t = threadIdx.x;
    if (t == 0) {
        int allzero = 1;
        for (int i = 1; i < 256; i += 2)
            if (sl[i] != 0 || tl[i] != 0) { allzero = 0; break; }
        g_lmode = allzero;   // int64 labels 0..4 -> all odd 32-bit words zero
        g_done = 0;
    }
    if (t < NCLS*NC) g_clsum[t] = 0.f;
    if (t < NCLS)    g_clcnt[t] = 0.f;
    if (t < 2)       g_acc[t]   = 0.f;
}

// ---------------- K1: normalize + transpose + bf16 hi/lo split (+ teacher class sums) ----------------
__global__ __launch_bounds__(256) void k_norm(const float* __restrict__ s_in,
                                              const float* __restrict__ t_in,
                                              const void* __restrict__ tl) {
    __shared__ float sh[NC][33];
    __shared__ float part[8][32];
    __shared__ float invn[32];
    __shared__ float cls[NCLS][NC];
    __shared__ int lbls[32];
    int stu = (blockIdx.y == 0);
    const float* in   = stu ? s_in : t_in;
    float*       outf = stu ? g_s : 0;
    __nv_bfloat16* outh = stu ? g_sh : g_th;
    __nv_bfloat16* outl = stu ? g_sl : g_tl;
    const float scale = stu ? S_SCALE : 1.0f;
    int b   = blockIdx.x >> 5;
    int hw0 = (blockIdx.x & 31) << 5;
    int n0  = b * NHW + hw0;
    int tx = threadIdx.x & 31, ty = threadIdx.x >> 5;

    if (!stu) {
        for (int q = threadIdx.x; q < NCLS*NC; q += 256) ((float*)cls)[q] = 0.f;
        if (threadIdx.x < 32) {
            int l = get_label(tl, n0 + threadIdx.x);
            lbls[threadIdx.x] = min(max(l, 0), NCLS - 1);
        }
    }

    float p = 0.f;
    const float* base = in + (size_t)b * NC * NHW + hw0 + tx;
    for (int c = ty; c < NC; c += 8) {
        float v = base[(size_t)c * NHW];
        sh[c][tx] = v;
        p += v * v;
    }
    part[ty][tx] = p;
    __syncthreads();
    if (ty == 0) {
        float s = 0.f;
        #pragma unroll
        for (int q = 0; q < 8; q++) s += part[q][tx];
        invn[tx] = rsqrtf(s) * scale;
    }
    __syncthreads();
    for (int idx = threadIdx.x; idx < NC * 32; idx += 256) {
        int c = idx & 127, q = idx >> 7;
        float v = sh[c][q] * invn[q];
        size_t o = (size_t)(n0 + q) * NC + c;
        __nv_bfloat16 h = __float2bfloat16(v);
        outh[o] = h;
        outl[o] = __float2bfloat16(v - __bfloat162float(h));
        if (stu) outf[o] = v;
        else atomicAdd(&cls[lbls[q]][c], v);
    }
    if (!stu) {
        __syncthreads();
        for (int q = threadIdx.x; q < NCLS*NC; q += 256)
            atomicAdd(&g_clsum[q], ((float*)cls)[q]);
        if (threadIdx.x < 32)
            atomicAdd(&g_clcnt[lbls[threadIdx.x]], 1.f);
    }
}

// ---------------- K2: warp-MMA bf16 split GEMM + exp2 + row-sum ----------------
// grid = 128 blocks: block b -> i-tile (b>>1), j-half (b&1). One wave on 148 SMs.
// Per j-tile: D[128,128] = S_hi T_hi^T + S_hi T_lo^T + S_lo T_hi^T (fp32 accum);
// logits carry log2e so epilogue is bare ex2. Frag-sharing inner loop:
// per k-step load A_hi/A_lo/B_hi/B_lo once -> 12 LDSM per 48 MMAs.
extern __shared__ char smem_raw[];

__global__ __launch_bounds__(256, 1) void k_main() {
    unsigned sbase = (unsigned)__cvta_generic_to_shared(smem_raw);
    int tid = threadIdx.x, lane = tid & 31, wid = tid >> 5;
    int i0    = (blockIdx.x >> 1) * BM;
    int jhalf = blockIdx.x & 1;
    int jbase = jhalf * (NTOT / 2);
    int wr = wid & 1, wc = wid >> 1;
    int m_base = wr * 64, n_base = wc * 32;
    int sub = lane >> 3, l7 = lane & 7;

    // ldmatrix per-lane address bases (validated layout from R8 pass)
    unsigned a_rel[4]; int a_sw[4];
    #pragma unroll
    for (int mf = 0; mf < 4; mf++) {
        int row = m_base + mf * 16 + (sub & 1) * 8 + l7;
        a_rel[mf] = row * 256; a_sw[mf] = row & 7;
    }
    const int a_co = sub >> 1;
    unsigned b_rel[2]; int b_sw[2];
    #pragma unroll
    for (int p = 0; p < 2; p++) {
        int row = n_base + p * 16 + (sub >> 1) * 8 + l7;
        b_rel[p] = row * 256; b_sw[p] = row & 7;
    }
    const int b_co = sub & 1;

    // prologue: A(hi,lo) resident + B tile 0 (hi,lo)
    load_tile(sbase + SM_A,         g_sh + (size_t)i0 * NC, tid);
    load_tile(sbase + SM_A + 32768, g_sl + (size_t)i0 * NC, tid);
    load_tile(sbase + SM_B0,         g_th + (size_t)jbase * NC, tid);
    load_tile(sbase + SM_B0 + 32768, g_tl + (size_t)jbase * NC, tid);
    cpcommit();

    float rs[8];
    #pragma unroll
    for (int q = 0; q < 8; q++) rs[q] = 0.f;

    for (int jt = 0; jt < NT; jt++) {
        int b = jt & 1;
        cpwait<0>();
        __syncthreads();   // B(jt) visible; all warps done reading buf b^1

        if (jt + 1 < NT) { // prefetch B(jt+1) into the other buffer (overlaps MMA)
            int j0 = jbase + (jt + 1) * BN;
            unsigned dst = sbase + ((b ^ 1) ? SM_B1 : SM_B0);
            load_tile(dst,         g_th + (size_t)j0 * NC, tid);
            load_tile(dst + 32768, g_tl + (size_t)j0 * NC, tid);
            cpcommit();
        }

        unsigned Ah = sbase + SM_A, Al = Ah + 32768u;
        unsigned Bh = sbase + (b ? SM_B1 : SM_B0), Bl = Bh + 32768u;
        float c[4][4][4];
        #pragma unroll
        for (int mf = 0; mf < 4; mf++)
            #pragma unroll
            for (int nf = 0; nf < 4; nf++)
                #pragma unroll
                for (int q = 0; q < 4; q++) c[mf][nf][q] = 0.f;

        #pragma unroll
        for (int ks = 0; ks < 8; ks++) {
            unsigned ah[4][4], al[4][4], bh[2][4], bl[2][4];
            #pragma unroll
            for (int mf = 0; mf < 4; mf++) {
                unsigned off = a_rel[mf] + (((2*ks + a_co) ^ a_sw[mf]) << 4);
                ldsm4(ah[mf], Ah + off);
                ldsm4(al[mf], Al + off);
            }
            #pragma unroll
            for (int p = 0; p < 2; p++) {
                unsigned off = b_rel[p] + (((2*ks + b_co) ^ b_sw[p]) << 4);
                ldsm4(bh[p], Bh + off);
                ldsm4(bl[p], Bl + off);
            }
            #pragma unroll
            for (int mf = 0; mf < 4; mf++) {
                // term0: S_hi * T_hi
                mma16816(c[mf][0], ah[mf], bh[0][0], bh[0][1]);
                mma16816(c[mf][1], ah[mf], bh[0][2], bh[0][3]);
                mma16816(c[mf][2], ah[mf], bh[1][0], bh[1][1]);
                mma16816(c[mf][3], ah[mf], bh[1][2], bh[1][3]);
                // term1: S_hi * T_lo
                mma16816(c[mf][0], ah[mf], bl[0][0], bl[0][1]);
                mma16816(c[mf][1], ah[mf], bl[0][2], bl[0][3]);
                mma16816(c[mf][2], ah[mf], bl[1][0], bl[1][1]);
                mma16816(c[mf][3], ah[mf], bl[1][2], bl[1][3]);
                // term2: S_lo * T_hi
                mma16816(c[mf][0], al[mf], bh[0][0], bh[0][1]);
                mma16816(c[mf][1], al[mf], bh[0][2], bh[0][3]);
                mma16816(c[mf][2], al[mf], bh[1][0], bh[1][1]);
                mma16816(c[mf][3], al[mf], bh[1][2], bh[1][3]);
            }
        }
        // 2^y accumulate (y = logit*log2e, |y|<=14.5 -> fp32 safe; no max pass)
        #pragma unroll
        for (int mf = 0; mf < 4; mf++) {
            float e0 = 0.f, e1 = 0.f;
            #pragma unroll
            for (int nf = 0; nf < 4; nf++) {
                e0 += ex2f(c[mf][nf][0]) + ex2f(c[mf][nf][1]);
                e1 += ex2f(c[mf][nf][2]) + ex2f(c[mf][nf][3]);
            }
            rs[mf*2]   += e0;   // row = m_base + mf*16 + lane/4
            rs[mf*2+1] += e1;   // row = m_base + mf*16 + lane/4 + 8
        }
    }

    __syncthreads();                      // SMEM reads done -> reuse as reduce space
    float* red = (float*)smem_raw;        // [128][4]
    #pragma unroll
    for (int q = 0; q < 8; q++) {
        rs[q] += __shfl_xor_sync(0xFFFFFFFFu, rs[q], 1);
        rs[q] += __shfl_xor_sync(0xFFFFFFFFu, rs[q], 2);
    }
    if ((lane & 3) == 0) {
        int r0 = m_base + (lane >> 2);
        #pragma unroll
        for (int mf = 0; mf < 4; mf++) {
            red[(r0 + mf*16    ) * 4 + wc] = rs[mf*2];
            red[(r0 + mf*16 + 8) * 4 + wc] = rs[mf*2+1];
        }
    }
    __syncthreads();
    if (tid < BM) {
        float s = red[tid*4] + red[tid*4+1] + red[tid*4+2] + red[tid*4+3];
        g_sep[jhalf * NTOT + i0 + tid] = s;   // single writer: deterministic
    }
}

// ---------------- K3: per-anchor terms + reduction + loss (completion counter) ----------------
__global__ __launch_bounds__(256) void k_final(const void* sl, float* out) {
    int i = blockIdx.x * 256 + threadIdx.x;
    int lbl = get_label(sl, i);
    int lc = min(max(lbl, 0), NCLS - 1);
    float cnt = g_clcnt[lc];
    float lse = logf(g_sep[i] + g_sep[NTOT + i]);   // natural log of sum of 2^y = sum e^logit
    const float4* sv = (const float4*)(g_s + (size_t)i * NC);
    const float4* cv = (const float4*)(g_clsum + lc * NC);
    float dot = 0.f;   // scaled by S_SCALE (=1/T * log2e); *LN2 restores 1/T-scaled logits
    #pragma unroll
    for (int q = 0; q < 32; q++) {
        float4 a = sv[q], b = cv[q];
        dot += a.x * b.x + a.y * b.y + a.z * b.z + a.w * b.w;
    }
    float mlpp = (dot * LN2 - cnt * lse) / (cnt + 1e-8f);
    float w = (cnt > 1e-8f && lbl != 0) ? 1.f : 0.f;

    __shared__ float r1[256], r2[256];
    r1[threadIdx.x] = w * mlpp;
    r2[threadIdx.x] = w;
    __syncthreads();
    for (int s = 128; s > 0; s >>= 1) {
        if (threadIdx.x < s) {
            r1[threadIdx.x] += r1[threadIdx.x + s];
            r2[threadIdx.x] += r2[threadIdx.x + s];
        }
        __syncthreads();
    }
    if (threadIdx.x == 0) {
        atomicAdd(&g_acc[0], r1[0]);
        atomicAdd(&g_acc[1], r2[0]);
        __threadfence();
        int done = atomicAdd(&g_done, 1);
        if (done == (int)gridDim.x - 1) {
            __threadfence();
            out[0] = -g_acc[0] / g_acc[1];
        }
    }
}

// ---------------- launch ----------------
extern "C" void kernel_launch(void* const* d_in, const int* in_sizes, int n_in,
                              void* d_out, int out_size) {
    const float* s_in = (const float*)d_in[0];
    const float* t_in = (const float*)d_in[1];
    const void*  sl   = d_in[2];
    const void*  tl   = d_in[3];
    float* out = (float*)d_out;

    cudaFuncSetAttribute(k_main, cudaFuncAttributeMaxDynamicSharedMemorySize, SMEM_TOTAL);

    k_init<<<1, 640>>>((const int*)sl, (const int*)tl);
    k_norm<<<dim3(256, 2), 256>>>(s_in, t_in, tl);
    k_main<<<(NTOT / BM) * 2, 256, SMEM_TOTAL>>>();
    k_final<<<NTOT / 256, 256>>>(sl, out);
}

// round 10
// speedup vs baseline: 4.5505x; 1.3342x over previous
#include <cuda_runtime.h>
#include <cuda_bf16.h>
#include <math.h>

// Problem shape (fixed by dataset)
#define NB   8
#define NC   128
#define NHW  1024
#define NTOT (NB*NHW)      // 8192
#define NCLS 5
// student scale = (1/T) * log2(e): epilogue is bare ex2.approx
#define S_SCALE (10.0f * 1.4426950408889634f)
#define LN2 0.6931471805599453f

#define BM 128             // i-rows per block
#define BN 128             // j-cols per tile
#define NT 32              // j-tiles per block (each block covers half the j range)

// dynamic smem layout (bytes): A_hi resident + B double-buffered (hi,lo)
#define SM_A   0           // Ahi 32768
#define SM_B0  32768       // B0hi 32768 | B0lo 32768
#define SM_B1  98304       // B1hi 32768 | B1lo 32768
#define SMEM_TOTAL 163840

// ---------------- device scratch (no allocations allowed) ----------------
__device__ float g_s[NTOT*NC];            // student fp32, *S_SCALE (k_final dot)
__device__ __nv_bfloat16 g_sh[NTOT*NC];                  // student hi bf16 (*S_SCALE)
__device__ __nv_bfloat16 g_th[NTOT*NC], g_tl[NTOT*NC];   // teacher hi/lo bf16
__device__ float g_sep[2*NTOT];           // partial sum-of-exp (half, i); single writer
__device__ float g_clsum[NCLS*NC];
__device__ float g_clcnt[NCLS];
__device__ float g_acc[2];
__device__ int   g_done;
__device__ int   g_lmode;

// ---------------- helpers ----------------
__device__ __forceinline__ void cpasync16(unsigned smem, const void* g) {
    asm volatile("cp.async.cg.shared.global [%0], [%1], 16;\n" :: "r"(smem), "l"(g));
}
__device__ __forceinline__ void cpcommit() {
    asm volatile("cp.async.commit_group;\n" ::: "memory");
}
template<int N> __device__ __forceinline__ void cpwait() {
    asm volatile("cp.async.wait_group %0;\n" :: "n"(N) : "memory");
}
__device__ __forceinline__ int get_label(const void* p, int i) {
    if (g_lmode) return (int)(((const long long*)p)[i]);
    return ((const int*)p)[i];
}
__device__ __forceinline__ void ldsm4(unsigned* r, unsigned addr) {
    asm volatile("ldmatrix.sync.aligned.m8n8.x4.shared.b16 {%0,%1,%2,%3}, [%4];"
                 : "=r"(r[0]), "=r"(r[1]), "=r"(r[2]), "=r"(r[3]) : "r"(addr));
}
__device__ __forceinline__ void mma16816(float* c, const unsigned* a, unsigned b0, unsigned b1) {
    asm volatile("mma.sync.aligned.m16n8k16.row.col.f32.bf16.bf16.f32 "
                 "{%0,%1,%2,%3}, {%4,%5,%6,%7}, {%8,%9}, {%0,%1,%2,%3};"
                 : "+f"(c[0]), "+f"(c[1]), "+f"(c[2]), "+f"(c[3])
                 : "r"(a[0]), "r"(a[1]), "r"(a[2]), "r"(a[3]), "r"(b0), "r"(b1));
}
__device__ __forceinline__ float ex2f(float x) {
    float y; asm("ex2.approx.f32 %0, %1;" : "=f"(y) : "f"(x)); return y;
}

// Load one 128x128 bf16 tile (row-major [row][128]) into SMEM.
// Row = 256B = 16 chunks of 16B; chunk swizzle c' = c ^ (row & 7):
// 8 consecutive rows at a fixed chunk hit 8 distinct bank groups (ldmatrix conflict-free).
__device__ __forceinline__ void load_tile(unsigned dst, const __nv_bfloat16* src, int tid) {
    #pragma unroll
    for (int it = 0; it < 8; it++) {
        int idx = tid + it * 256;
        int row = idx >> 4, c = idx & 15;
        unsigned off = (unsigned)(row * 256 + ((c ^ (row & 7)) << 4));
        cpasync16(dst + off, (const char*)src + row * 256 + c * 16);
    }
}

// ---------------- K0: label dtype probe + zero accumulators ----------------
__global__ void k_init(const int* sl, const int* tl) {
    int t = threadIdx.x;
    if (t == 0) {
        int allzero = 1;
        for (int i = 1; i < 256; i += 2)
            if (sl[i] != 0 || tl[i] != 0) { allzero = 0; break; }
        g_lmode = allzero;   // int64 labels 0..4 -> all odd 32-bit words zero
        g_done = 0;
    }
    if (t < NCLS*NC) g_clsum[t] = 0.f;
    if (t < NCLS)    g_clcnt[t] = 0.f;
    if (t < 2)       g_acc[t]   = 0.f;
}

// ---------------- K1: normalize + transpose + bf16 split (+ teacher class sums) ----------------
__global__ __launch_bounds__(256) void k_norm(const float* __restrict__ s_in,
                                              const float* __restrict__ t_in,
                                              const void* __restrict__ tl) {
    __shared__ float sh[NC][33];
    __shared__ float part[8][32];
    __shared__ float invn[32];
    __shared__ float cls[NCLS][NC];
    __shared__ int lbls[32];
    int stu = (blockIdx.y == 0);
    const float* in   = stu ? s_in : t_in;
    __nv_bfloat16* outh = stu ? g_sh : g_th;
    const float scale = stu ? S_SCALE : 1.0f;
    int b   = blockIdx.x >> 5;
    int hw0 = (blockIdx.x & 31) << 5;
    int n0  = b * NHW + hw0;
    int tx = threadIdx.x & 31, ty = threadIdx.x >> 5;

    if (!stu) {
        for (int q = threadIdx.x; q < NCLS*NC; q += 256) ((float*)cls)[q] = 0.f;
        if (threadIdx.x < 32) {
            int l = get_label(tl, n0 + threadIdx.x);
            lbls[threadIdx.x] = min(max(l, 0), NCLS - 1);
        }
    }

    float p = 0.f;
    const float* base = in + (size_t)b * NC * NHW + hw0 + tx;
    for (int c = ty; c < NC; c += 8) {
        float v = base[(size_t)c * NHW];
        sh[c][tx] = v;
        p += v * v;
    }
    part[ty][tx] = p;
    __syncthreads();
    if (ty == 0) {
        float s = 0.f;
        #pragma unroll
        for (int q = 0; q < 8; q++) s += part[q][tx];
        invn[tx] = rsqrtf(s) * scale;
    }
    __syncthreads();
    for (int idx = threadIdx.x; idx < NC * 32; idx += 256) {
        int c = idx & 127, q = idx >> 7;
        float v = sh[c][q] * invn[q];
        size_t o = (size_t)(n0 + q) * NC + c;
        __nv_bfloat16 h = __float2bfloat16(v);
        outh[o] = h;
        if (stu) {
            g_s[o] = v;                       // exact numerator path
        } else {
            g_tl[o] = __float2bfloat16(v - __bfloat162float(h));
            atomicAdd(&cls[lbls[q]][c], v);
        }
    }
    if (!stu) {
        __syncthreads();
        for (int q = threadIdx.x; q < NCLS*NC; q += 256)
            atomicAdd(&g_clsum[q], ((float*)cls)[q]);
        if (threadIdx.x < 32)
            atomicAdd(&g_clcnt[lbls[threadIdx.x]], 1.f);
    }
}

// ---------------- K2: warp-MMA 2-term bf16 GEMM + exp2 + row-sum ----------------
// grid = 128 blocks: block b -> i-tile (b>>1), j-half (b&1). One wave on 148 SMs.
// Per j-tile: D[128,128] = S_hi T_hi^T + S_hi T_lo^T (fp32 accum); the dropped
// S_lo T_hi term contributes ~1e-3 (log2 units) zero-mean noise to logits that
// are only used inside lse -> loss rel err ~1e-5. Logits carry log2e -> bare ex2.
extern __shared__ char smem_raw[];

__global__ __launch_bounds__(256, 1) void k_main() {
    unsigned sbase = (unsigned)__cvta_generic_to_shared(smem_raw);
    int tid = threadIdx.x, lane = tid & 31, wid = tid >> 5;
    int i0    = (blockIdx.x >> 1) * BM;
    int jhalf = blockIdx.x & 1;
    int jbase = jhalf * (NTOT / 2);
    int wr = wid & 1, wc = wid >> 1;
    int m_base = wr * 64, n_base = wc * 32;
    int sub = lane >> 3, l7 = lane & 7;

    // ldmatrix per-lane address bases (layout validated in R8/R9 passes)
    unsigned a_rel[4]; int a_sw[4];
    #pragma unroll
    for (int mf = 0; mf < 4; mf++) {
        int row = m_base + mf * 16 + (sub & 1) * 8 + l7;
        a_rel[mf] = row * 256; a_sw[mf] = row & 7;
    }
    const int a_co = sub >> 1;
    unsigned b_rel[2]; int b_sw[2];
    #pragma unroll
    for (int p = 0; p < 2; p++) {
        int row = n_base + p * 16 + (sub >> 1) * 8 + l7;
        b_rel[p] = row * 256; b_sw[p] = row & 7;
    }
    const int b_co = sub & 1;

    // prologue: A_hi resident + B tile 0 (hi,lo)
    load_tile(sbase + SM_A,          g_sh + (size_t)i0 * NC, tid);
    load_tile(sbase + SM_B0,         g_th + (size_t)jbase * NC, tid);
    load_tile(sbase + SM_B0 + 32768, g_tl + (size_t)jbase * NC, tid);
    cpcommit();

    float rs[8];
    #pragma unroll
    for (int q = 0; q < 8; q++) rs[q] = 0.f;

    for (int jt = 0; jt < NT; jt++) {
        int b = jt & 1;
        cpwait<0>();
        __syncthreads();   // B(jt) visible; all warps done reading buf b^1

        if (jt + 1 < NT) { // prefetch B(jt+1) into the other buffer (overlaps MMA)
            int j0 = jbase + (jt + 1) * BN;
            unsigned dst = sbase + ((b ^ 1) ? SM_B1 : SM_B0);
            load_tile(dst,         g_th + (size_t)j0 * NC, tid);
            load_tile(dst + 32768, g_tl + (size_t)j0 * NC, tid);
            cpcommit();
        }

        unsigned Ah = sbase + SM_A;
        unsigned Bh = sbase + (b ? SM_B1 : SM_B0), Bl = Bh + 32768u;
        float c[4][4][4];
        #pragma unroll
        for (int mf = 0; mf < 4; mf++)
            #pragma unroll
            for (int nf = 0; nf < 4; nf++)
                #pragma unroll
                for (int q = 0; q < 4; q++) c[mf][nf][q] = 0.f;

        #pragma unroll
        for (int ks = 0; ks < 8; ks++) {
            unsigned ah[4][4], bh[2][4], bl[2][4];
            #pragma unroll
            for (int mf = 0; mf < 4; mf++)
                ldsm4(ah[mf], Ah + a_rel[mf] + (((2*ks + a_co) ^ a_sw[mf]) << 4));
            #pragma unroll
            for (int p = 0; p < 2; p++) {
                unsigned off = b_rel[p] + (((2*ks + b_co) ^ b_sw[p]) << 4);
                ldsm4(bh[p], Bh + off);
                ldsm4(bl[p], Bl + off);
            }
            #pragma unroll
            for (int mf = 0; mf < 4; mf++) {
                // term0: S_hi * T_hi
                mma16816(c[mf][0], ah[mf], bh[0][0], bh[0][1]);
                mma16816(c[mf][1], ah[mf], bh[0][2], bh[0][3]);
                mma16816(c[mf][2], ah[mf], bh[1][0], bh[1][1]);
                mma16816(c[mf][3], ah[mf], bh[1][2], bh[1][3]);
                // term1: S_hi * T_lo
                mma16816(c[mf][0], ah[mf], bl[0][0], bl[0][1]);
                mma16816(c[mf][1], ah[mf], bl[0][2], bl[0][3]);
                mma16816(c[mf][2], ah[mf], bl[1][0], bl[1][1]);
                mma16816(c[mf][3], ah[mf], bl[1][2], bl[1][3]);
            }
        }
        // 2^y accumulate (y = logit*log2e, |y|<=14.5 -> fp32 safe; no max pass)
        #pragma unroll
        for (int mf = 0; mf < 4; mf++) {
            float e0 = 0.f, e1 = 0.f;
            #pragma unroll
            for (int nf = 0; nf < 4; nf++) {
                e0 += ex2f(c[mf][nf][0]) + ex2f(c[mf][nf][1]);
                e1 += ex2f(c[mf][nf][2]) + ex2f(c[mf][nf][3]);
            }
            rs[mf*2]   += e0;   // row = m_base + mf*16 + lane/4
            rs[mf*2+1] += e1;   // row = m_base + mf*16 + lane/4 + 8
        }
    }

    __syncthreads();                      // SMEM reads done -> reuse as reduce space
    float* red = (float*)smem_raw;        // [128][4]
    #pragma unroll
    for (int q = 0; q < 8; q++) {
        rs[q] += __shfl_xor_sync(0xFFFFFFFFu, rs[q], 1);
        rs[q] += __shfl_xor_sync(0xFFFFFFFFu, rs[q], 2);
    }
    if ((lane & 3) == 0) {
        int r0 = m_base + (lane >> 2);
        #pragma unroll
        for (int mf = 0; mf < 4; mf++) {
            red[(r0 + mf*16    ) * 4 + wc] = rs[mf*2];
            red[(r0 + mf*16 + 8) * 4 + wc] = rs[mf*2+1];
        }
    }
    __syncthreads();
    if (tid < BM) {
        float s = red[tid*4] + red[tid*4+1] + red[tid*4+2] + red[tid*4+3];
        g_sep[jhalf * NTOT + i0 + tid] = s;   // single writer: deterministic
    }
}

// ---------------- K3: warp-per-row anchor terms + reduction + loss ----------------
__global__ __launch_bounds__(256) void k_final(const void* sl, float* out) {
    int wid = threadIdx.x >> 5, lane = threadIdx.x & 31;
    int row = blockIdx.x * 8 + wid;
    int lbl = 0;
    if (lane == 0) lbl = get_label(sl, row);
    lbl = __shfl_sync(0xFFFFFFFFu, lbl, 0);
    int lc = min(max(lbl, 0), NCLS - 1);

    float4 a = ((const float4*)(g_s + (size_t)row * NC))[lane];
    float4 b = ((const float4*)(g_clsum + lc * NC))[lane];
    float dot = a.x*b.x + a.y*b.y + a.z*b.z + a.w*b.w;
    #pragma unroll
    for (int o = 16; o > 0; o >>= 1) dot += __shfl_xor_sync(0xFFFFFFFFu, dot, o);

    __shared__ float r1s[8], r2s[8];
    if (lane == 0) {
        float cnt = g_clcnt[lc];
        float lse = logf(g_sep[row] + g_sep[NTOT + row]);  // ln of sum 2^y = sum e^logit
        float mlpp = (dot * LN2 - cnt * lse) / (cnt + 1e-8f);
        float w = (cnt > 1e-8f && lbl != 0) ? 1.f : 0.f;
        r1s[wid] = w * mlpp;
        r2s[wid] = w;
    }
    __syncthreads();
    if (threadIdx.x == 0) {
        float s1 = 0.f, s2 = 0.f;
        #pragma unroll
        for (int q = 0; q < 8; q++) { s1 += r1s[q]; s2 += r2s[q]; }
        atomicAdd(&g_acc[0], s1);
        atomicAdd(&g_acc[1], s2);
        __threadfence();
        if (atomicAdd(&g_done, 1) == (int)gridDim.x - 1) {
            __threadfence();
            out[0] = -g_acc[0] / g_acc[1];
        }
    }
}

// ---------------- launch ----------------
extern "C" void kernel_launch(void* const* d_in, const int* in_sizes, int n_in,
                              void* d_out, int out_size) {
    const float* s_in = (const float*)d_in[0];
    const float* t_in = (const float*)d_in[1];
    const void*  sl   = d_in[2];
    const void*  tl   = d_in[3];
    float* out = (float*)d_out;

    cudaFuncSetAttribute(k_main, cudaFuncAttributeMaxDynamicSharedMemorySize, SMEM_TOTAL);

    k_init<<<1, 640>>>((const int*)sl, (const int*)tl);
    k_norm<<<dim3(256, 2), 256>>>(s_in, t_in, tl);
    k_main<<<(NTOT / BM) * 2, 256, SMEM_TOTAL>>>();
    k_final<<<NTOT / 8, 256>>>(sl, out);
}

// round 11
// speedup vs baseline: 6.9445x; 1.5261x over previous
#include <cuda_runtime.h>
#include <cuda_bf16.h>
#include <math.h>

// Problem shape (fixed by dataset)
#define NB   8
#define NC   128
#define NHW  1024
#define NTOT (NB*NHW)      // 8192
#define NCLS 5
// student scale = (1/T) * log2(e): epilogue is bare ex2.approx
#define S_SCALE (10.0f * 1.4426950408889634f)
#define LN2 0.6931471805599453f

#define BM 128             // i-rows per block
#define BN 128             // j-cols per tile
#define NT 32              // j-tiles per block (each block covers half the j range)

// dynamic smem layout (bytes): A_hi resident + B_hi double-buffered
#define SM_A   0           // Ahi 32768
#define SM_B0  32768       // B0hi 32768
#define SM_B1  65536       // B1hi 32768
#define SMEM_TOTAL 98304

// ---------------- device scratch (no allocations allowed) ----------------
__device__ float g_s[NTOT*NC];            // student fp32, *S_SCALE (exact numerator path)
__device__ __nv_bfloat16 g_sh[NTOT*NC];   // student bf16 (*S_SCALE)
__device__ __nv_bfloat16 g_th[NTOT*NC];   // teacher bf16
__device__ float g_sep[2*NTOT];           // partial sum-of-exp (half, i); single writer
__device__ float g_clsum[NCLS*NC];
__device__ float g_clcnt[NCLS];
__device__ float g_acc[2];
__device__ int   g_done;
__device__ int   g_lmode;

// ---------------- helpers ----------------
__device__ __forceinline__ void cpasync16(unsigned smem, const void* g) {
    asm volatile("cp.async.cg.shared.global [%0], [%1], 16;\n" :: "r"(smem), "l"(g));
}
__device__ __forceinline__ void cpcommit() {
    asm volatile("cp.async.commit_group;\n" ::: "memory");
}
template<int N> __device__ __forceinline__ void cpwait() {
    asm volatile("cp.async.wait_group %0;\n" :: "n"(N) : "memory");
}
__device__ __forceinline__ int get_label(const void* p, int i) {
    if (g_lmode) return (int)(((const long long*)p)[i]);
    return ((const int*)p)[i];
}
__device__ __forceinline__ void ldsm4(unsigned* r, unsigned addr) {
    asm volatile("ldmatrix.sync.aligned.m8n8.x4.shared.b16 {%0,%1,%2,%3}, [%4];"
                 : "=r"(r[0]), "=r"(r[1]), "=r"(r[2]), "=r"(r[3]) : "r"(addr));
}
__device__ __forceinline__ void mma16816(float* c, const unsigned* a, unsigned b0, unsigned b1) {
    asm volatile("mma.sync.aligned.m16n8k16.row.col.f32.bf16.bf16.f32 "
                 "{%0,%1,%2,%3}, {%4,%5,%6,%7}, {%8,%9}, {%0,%1,%2,%3};"
                 : "+f"(c[0]), "+f"(c[1]), "+f"(c[2]), "+f"(c[3])
                 : "r"(a[0]), "r"(a[1]), "r"(a[2]), "r"(a[3]), "r"(b0), "r"(b1));
}
__device__ __forceinline__ float ex2f(float x) {
    float y; asm("ex2.approx.f32 %0, %1;" : "=f"(y) : "f"(x)); return y;
}

// Load one 128x128 bf16 tile (row-major [row][128]) into SMEM.
// Row = 256B = 16 chunks of 16B; chunk swizzle c' = c ^ (row & 7):
// 8 consecutive rows at a fixed chunk hit 8 distinct bank groups (ldmatrix conflict-free).
__device__ __forceinline__ void load_tile(unsigned dst, const __nv_bfloat16* src, int tid) {
    #pragma unroll
    for (int it = 0; it < 8; it++) {
        int idx = tid + it * 256;
        int row = idx >> 4, c = idx & 15;
        unsigned off = (unsigned)(row * 256 + ((c ^ (row & 7)) << 4));
        cpasync16(dst + off, (const char*)src + row * 256 + c * 16);
    }
}

// ---------------- K0: label dtype probe + zero accumulators ----------------
__global__ void k_init(const int* sl, const int* tl) {
    int t = threadIdx.x;
    if (t == 0) {
        int allzero = 1;
        for (int i = 1; i < 256; i += 2)
            if (sl[i] != 0 || tl[i] != 0) { allzero = 0; break; }
        g_lmode = allzero;   // int64 labels 0..4 -> all odd 32-bit words zero
        g_done = 0;
    }
    if (t < NCLS*NC) g_clsum[t] = 0.f;
    if (t < NCLS)    g_clcnt[t] = 0.f;
    if (t < 2)       g_acc[t]   = 0.f;
}

// ---------------- K1: normalize + transpose + bf16 (+ teacher class sums) ----------------
__global__ __launch_bounds__(256) void k_norm(const float* __restrict__ s_in,
                                              const float* __restrict__ t_in,
                                              const void* __restrict__ tl) {
    __shared__ float sh[NC][33];
    __shared__ float part[8][32];
    __shared__ float invn[32];
    __shared__ float cls[NCLS][NC];
    __shared__ int lbls[32];
    int stu = (blockIdx.y == 0);
    const float* in   = stu ? s_in : t_in;
    __nv_bfloat16* outh = stu ? g_sh : g_th;
    const float scale = stu ? S_SCALE : 1.0f;
    int b   = blockIdx.x >> 5;
    int hw0 = (blockIdx.x & 31) << 5;
    int n0  = b * NHW + hw0;
    int tx = threadIdx.x & 31, ty = threadIdx.x >> 5;

    if (!stu) {
        for (int q = threadIdx.x; q < NCLS*NC; q += 256) ((float*)cls)[q] = 0.f;
        if (threadIdx.x < 32) {
            int l = get_label(tl, n0 + threadIdx.x);
            lbls[threadIdx.x] = min(max(l, 0), NCLS - 1);
        }
    }

    float p = 0.f;
    const float* base = in + (size_t)b * NC * NHW + hw0 + tx;
    for (int c = ty; c < NC; c += 8) {
        float v = base[(size_t)c * NHW];
        sh[c][tx] = v;
        p += v * v;
    }
    part[ty][tx] = p;
    __syncthreads();
    if (ty == 0) {
        float s = 0.f;
        #pragma unroll
        for (int q = 0; q < 8; q++) s += part[q][tx];
        invn[tx] = rsqrtf(s) * scale;
    }
    __syncthreads();
    for (int idx = threadIdx.x; idx < NC * 32; idx += 256) {
        int c = idx & 127, q = idx >> 7;
        float v = sh[c][q] * invn[q];
        size_t o = (size_t)(n0 + q) * NC + c;
        outh[o] = __float2bfloat16(v);
        if (stu) g_s[o] = v;                  // exact numerator path
        else     atomicAdd(&cls[lbls[q]][c], v);
    }
    if (!stu) {
        __syncthreads();
        for (int q = threadIdx.x; q < NCLS*NC; q += 256)
            atomicAdd(&g_clsum[q], ((float*)cls)[q]);
        if (threadIdx.x < 32)
            atomicAdd(&g_clcnt[lbls[threadIdx.x]], 1.f);
    }
}

// ---------------- K2: warp-MMA 1-term bf16 GEMM + exp2 + row-sum ----------------
// grid = 128 blocks: block b -> i-tile (b>>1), j-half (b&1). One wave on 148 SMs.
// Per j-tile: D[128,128] = S_bf16 T_bf16^T (fp32 accum). bf16 rounding adds
// ~2e-3 (log2 units) zero-mean noise per logit, used only inside lse whose
// weighted average kills it (measured: each split term dropped cost ~8e-7 rel).
// Numerator path stays exact fp32. Logits carry log2e -> bare ex2.
extern __shared__ char smem_raw[];

__global__ __launch_bounds__(256, 1) void k_main() {
    unsigned sbase = (unsigned)__cvta_generic_to_shared(smem_raw);
    int tid = threadIdx.x, lane = tid & 31, wid = tid >> 5;
    int i0    = (blockIdx.x >> 1) * BM;
    int jhalf = blockIdx.x & 1;
    int jbase = jhalf * (NTOT / 2);
    int wr = wid & 1, wc = wid >> 1;
    int m_base = wr * 64, n_base = wc * 32;
    int sub = lane >> 3, l7 = lane & 7;

    // ldmatrix per-lane address bases (layout validated in R8-R10 passes)
    unsigned a_rel[4]; int a_sw[4];
    #pragma unroll
    for (int mf = 0; mf < 4; mf++) {
        int row = m_base + mf * 16 + (sub & 1) * 8 + l7;
        a_rel[mf] = row * 256; a_sw[mf] = row & 7;
    }
    const int a_co = sub >> 1;
    unsigned b_rel[2]; int b_sw[2];
    #pragma unroll
    for (int p = 0; p < 2; p++) {
        int row = n_base + p * 16 + (sub >> 1) * 8 + l7;
        b_rel[p] = row * 256; b_sw[p] = row & 7;
    }
    const int b_co = sub & 1;

    // prologue: A resident + B tile 0
    load_tile(sbase + SM_A,  g_sh + (size_t)i0 * NC, tid);
    load_tile(sbase + SM_B0, g_th + (size_t)jbase * NC, tid);
    cpcommit();

    float rs[8];
    #pragma unroll
    for (int q = 0; q < 8; q++) rs[q] = 0.f;

    for (int jt = 0; jt < NT; jt++) {
        int b = jt & 1;
        cpwait<0>();
        __syncthreads();   // B(jt) visible; all warps done reading buf b^1

        if (jt + 1 < NT) { // prefetch B(jt+1) into the other buffer (overlaps MMA)
            int j0 = jbase + (jt + 1) * BN;
            load_tile(sbase + ((b ^ 1) ? SM_B1 : SM_B0), g_th + (size_t)j0 * NC, tid);
            cpcommit();
        }

        unsigned Ah = sbase + SM_A;
        unsigned Bh = sbase + (b ? SM_B1 : SM_B0);
        float c[4][4][4];
        #pragma unroll
        for (int mf = 0; mf < 4; mf++)
            #pragma unroll
            for (int nf = 0; nf < 4; nf++)
                #pragma unroll
                for (int q = 0; q < 4; q++) c[mf][nf][q] = 0.f;

        #pragma unroll
        for (int ks = 0; ks < 8; ks++) {
            unsigned ah[4][4], bh[2][4];
            #pragma unroll
            for (int mf = 0; mf < 4; mf++)
                ldsm4(ah[mf], Ah + a_rel[mf] + (((2*ks + a_co) ^ a_sw[mf]) << 4));
            #pragma unroll
            for (int p = 0; p < 2; p++)
                ldsm4(bh[p], Bh + b_rel[p] + (((2*ks + b_co) ^ b_sw[p]) << 4));
            #pragma unroll
            for (int mf = 0; mf < 4; mf++) {
                mma16816(c[mf][0], ah[mf], bh[0][0], bh[0][1]);
                mma16816(c[mf][1], ah[mf], bh[0][2], bh[0][3]);
                mma16816(c[mf][2], ah[mf], bh[1][0], bh[1][1]);
                mma16816(c[mf][3], ah[mf], bh[1][2], bh[1][3]);
            }
        }
        // 2^y accumulate (y = logit*log2e, |y|<=14.5 -> fp32 safe; no max pass)
        #pragma unroll
        for (int mf = 0; mf < 4; mf++) {
            float e0 = 0.f, e1 = 0.f;
            #pragma unroll
            for (int nf = 0; nf < 4; nf++) {
                e0 += ex2f(c[mf][nf][0]) + ex2f(c[mf][nf][1]);
                e1 += ex2f(c[mf][nf][2]) + ex2f(c[mf][nf][3]);
            }
            rs[mf*2]   += e0;   // row = m_base + mf*16 + lane/4
            rs[mf*2+1] += e1;   // row = m_base + mf*16 + lane/4 + 8
        }
    }

    __syncthreads();                      // SMEM reads done -> reuse as reduce space
    float* red = (float*)smem_raw;        // [128][4]
    #pragma unroll
    for (int q = 0; q < 8; q++) {
        rs[q] += __shfl_xor_sync(0xFFFFFFFFu, rs[q], 1);
        rs[q] += __shfl_xor_sync(0xFFFFFFFFu, rs[q], 2);
    }
    if ((lane & 3) == 0) {
        int r0 = m_base + (lane >> 2);
        #pragma unroll
        for (int mf = 0; mf < 4; mf++) {
            red[(r0 + mf*16    ) * 4 + wc] = rs[mf*2];
            red[(r0 + mf*16 + 8) * 4 + wc] = rs[mf*2+1];
        }
    }
    __syncthreads();
    if (tid < BM) {
        float s = red[tid*4] + red[tid*4+1] + red[tid*4+2] + red[tid*4+3];
        g_sep[jhalf * NTOT + i0 + tid] = s;   // single writer: deterministic
    }
}

// ---------------- K3: anchor terms (4 rows/warp, MLP=8) + reduction + loss ----------------
__global__ __launch_bounds__(256) void k_final(const void* sl, float* out) {
    int wid = threadIdx.x >> 5, lane = threadIdx.x & 31;
    int row0 = blockIdx.x * 32 + wid * 4;

    int lbl_own = 0;
    if (lane < 4) lbl_own = get_label(sl, row0 + lane);
    int lbl[4], lc[4];
    #pragma unroll
    for (int r = 0; r < 4; r++) {
        lbl[r] = __shfl_sync(0xFFFFFFFFu, lbl_own, r);
        lc[r] = min(max(lbl[r], 0), NCLS - 1);
    }

    float dot[4];
    #pragma unroll
    for (int r = 0; r < 4; r++) {
        float4 a = ((const float4*)(g_s + (size_t)(row0 + r) * NC))[lane];
        float4 b = ((const float4*)(g_clsum + lc[r] * NC))[lane];
        dot[r] = a.x*b.x + a.y*b.y + a.z*b.z + a.w*b.w;
    }
    #pragma unroll
    for (int r = 0; r < 4; r++)
        #pragma unroll
        for (int o = 16; o > 0; o >>= 1)
            dot[r] += __shfl_xor_sync(0xFFFFFFFFu, dot[r], o);

    __shared__ float r1s[8], r2s[8];
    if (lane == 0) {
        float s1 = 0.f, s2 = 0.f;
        #pragma unroll
        for (int r = 0; r < 4; r++) {
            int row = row0 + r;
            float cnt = g_clcnt[lc[r]];
            float lse = logf(g_sep[row] + g_sep[NTOT + row]);
            float mlpp = (dot[r] * LN2 - cnt * lse) / (cnt + 1e-8f);
            float w = (cnt > 1e-8f && lbl[r] != 0) ? 1.f : 0.f;
            s1 += w * mlpp; s2 += w;
        }
        r1s[wid] = s1; r2s[wid] = s2;
    }
    __syncthreads();
    if (threadIdx.x == 0) {
        float s1 = 0.f, s2 = 0.f;
        #pragma unroll
        for (int q = 0; q < 8; q++) { s1 += r1s[q]; s2 += r2s[q]; }
        atomicAdd(&g_acc[0], s1);
        atomicAdd(&g_acc[1], s2);
        __threadfence();
        if (atomicAdd(&g_done, 1) == (int)gridDim.x - 1) {
            __threadfence();
            out[0] = -g_acc[0] / g_acc[1];
        }
    }
}

// ---------------- launch ----------------
extern "C" void kernel_launch(void* const* d_in, const int* in_sizes, int n_in,
                              void* d_out, int out_size) {
    const float* s_in = (const float*)d_in[0];
    const float* t_in = (const float*)d_in[1];
    const void*  sl   = d_in[2];
    const void*  tl   = d_in[3];
    float* out = (float*)d_out;

    cudaFuncSetAttribute(k_main, cudaFuncAttributeMaxDynamicSharedMemorySize, SMEM_TOTAL);

    k_init<<<1, 640>>>((const int*)sl, (const int*)tl);
    k_norm<<<dim3(256, 2), 256>>>(s_in, t_in, tl);
    k_main<<<(NTOT / BM) * 2, 256, SMEM_TOTAL>>>();
    k_final<<<NTOT / 32, 256>>>(sl, out);
}

// round 12
// speedup vs baseline: 7.1111x; 1.0240x over previous
#include <cuda_runtime.h>
#include <cuda_bf16.h>
#include <math.h>

// Problem shape (fixed by dataset)
#define NB   8
#define NC   128
#define NHW  1024
#define NTOT (NB*NHW)      // 8192
#define NCLS 5
// student scale = (1/T) * log2(e): epilogue is bare ex2.approx
#define S_SCALE (10.0f * 1.4426950408889634f)
#define LN2 0.6931471805599453f

#define BM 128             // i-rows per block
#define BN 128             // j-cols per tile
#define NQ 4               // j-quarters (grid = 64 i-tiles * 4 quarters = 256 blocks)
#define NT 16              // j-tiles per block

// dynamic smem layout (bytes): A resident + B double-buffered
#define SM_A   0           // A 32768
#define SM_B0  32768       // B0 32768
#define SM_B1  65536       // B1 32768
#define SMEM_TOTAL 98304   // 96KB -> 2 blocks/SM co-resident

// ---------------- device scratch (no allocations allowed) ----------------
__device__ __nv_bfloat16 g_sh[NTOT*NC];   // student bf16 (*S_SCALE)
__device__ __nv_bfloat16 g_th[NTOT*NC];   // teacher bf16
__device__ float g_sep[NQ*NTOT];          // partial sum-of-exp (quarter, i); single writer
__device__ float g_clsum[NCLS*NC];
__device__ float g_clcnt[NCLS];
__device__ float g_acc[2];
__device__ int   g_done;
__device__ int   g_lmode;

// ---------------- helpers ----------------
__device__ __forceinline__ void cpasync16(unsigned smem, const void* g) {
    asm volatile("cp.async.cg.shared.global [%0], [%1], 16;\n" :: "r"(smem), "l"(g));
}
__device__ __forceinline__ void cpcommit() {
    asm volatile("cp.async.commit_group;\n" ::: "memory");
}
template<int N> __device__ __forceinline__ void cpwait() {
    asm volatile("cp.async.wait_group %0;\n" :: "n"(N) : "memory");
}
__device__ __forceinline__ int get_label(const void* p, int i) {
    if (g_lmode) return (int)(((const long long*)p)[i]);
    return ((const int*)p)[i];
}
__device__ __forceinline__ void ldsm4(unsigned* r, unsigned addr) {
    asm volatile("ldmatrix.sync.aligned.m8n8.x4.shared.b16 {%0,%1,%2,%3}, [%4];"
                 : "=r"(r[0]), "=r"(r[1]), "=r"(r[2]), "=r"(r[3]) : "r"(addr));
}
__device__ __forceinline__ void mma16816(float* c, const unsigned* a, unsigned b0, unsigned b1) {
    asm volatile("mma.sync.aligned.m16n8k16.row.col.f32.bf16.bf16.f32 "
                 "{%0,%1,%2,%3}, {%4,%5,%6,%7}, {%8,%9}, {%0,%1,%2,%3};"
                 : "+f"(c[0]), "+f"(c[1]), "+f"(c[2]), "+f"(c[3])
                 : "r"(a[0]), "r"(a[1]), "r"(a[2]), "r"(a[3]), "r"(b0), "r"(b1));
}
__device__ __forceinline__ float ex2f(float x) {
    float y; asm("ex2.approx.f32 %0, %1;" : "=f"(y) : "f"(x)); return y;
}

// Load one 128x128 bf16 tile (row-major [row][128]) into SMEM.
// Row = 256B = 16 chunks of 16B; chunk swizzle c' = c ^ (row & 7):
// 8 consecutive rows at a fixed chunk hit 8 distinct bank groups (ldmatrix conflict-free).
__device__ __forceinline__ void load_tile(unsigned dst, const __nv_bfloat16* src, int tid) {
    #pragma unroll
    for (int it = 0; it < 8; it++) {
        int idx = tid + it * 256;
        int row = idx >> 4, c = idx & 15;
        unsigned off = (unsigned)(row * 256 + ((c ^ (row & 7)) << 4));
        cpasync16(dst + off, (const char*)src + row * 256 + c * 16);
    }
}

// ---------------- K0: label dtype probe + zero accumulators ----------------
__global__ void k_init(const int* sl, const int* tl) {
    int t = threadIdx.x;
    if (t == 0) {
        int allzero = 1;
        for (int i = 1; i < 256; i += 2)
            if (sl[i] != 0 || tl[i] != 0) { allzero = 0; break; }
        g_lmode = allzero;   // int64 labels 0..4 -> all odd 32-bit words zero
        g_done = 0;
    }
    if (t < NCLS*NC) g_clsum[t] = 0.f;
    if (t < NCLS)    g_clcnt[t] = 0.f;
    if (t < 2)       g_acc[t]   = 0.f;
}

// ---------------- K1: normalize + transpose + bf16 (+ teacher class sums) ----------------
__global__ __launch_bounds__(256) void k_norm(const float* __restrict__ s_in,
                                              const float* __restrict__ t_in,
                                              const void* __restrict__ tl) {
    __shared__ float sh[NC][33];
    __shared__ float part[8][32];
    __shared__ float invn[32];
    __shared__ float cls[NCLS][NC];
    __shared__ int lbls[32];
    int stu = (blockIdx.y == 0);
    const float* in   = stu ? s_in : t_in;
    __nv_bfloat16* outh = stu ? g_sh : g_th;
    const float scale = stu ? S_SCALE : 1.0f;
    int b   = blockIdx.x >> 5;
    int hw0 = (blockIdx.x & 31) << 5;
    int n0  = b * NHW + hw0;
    int tx = threadIdx.x & 31, ty = threadIdx.x >> 5;

    if (!stu) {
        for (int q = threadIdx.x; q < NCLS*NC; q += 256) ((float*)cls)[q] = 0.f;
        if (threadIdx.x < 32) {
            int l = get_label(tl, n0 + threadIdx.x);
            lbls[threadIdx.x] = min(max(l, 0), NCLS - 1);
        }
    }

    float p = 0.f;
    const float* base = in + (size_t)b * NC * NHW + hw0 + tx;
    for (int c = ty; c < NC; c += 8) {
        float v = base[(size_t)c * NHW];
        sh[c][tx] = v;
        p += v * v;
    }
    part[ty][tx] = p;
    __syncthreads();
    if (ty == 0) {
        float s = 0.f;
        #pragma unroll
        for (int q = 0; q < 8; q++) s += part[q][tx];
        invn[tx] = rsqrtf(s) * scale;
    }
    __syncthreads();
    for (int idx = threadIdx.x; idx < NC * 32; idx += 256) {
        int c = idx & 127, q = idx >> 7;
        float v = sh[c][q] * invn[q];
        size_t o = (size_t)(n0 + q) * NC + c;
        outh[o] = __float2bfloat16(v);
        if (!stu) atomicAdd(&cls[lbls[q]][c], v);
    }
    if (!stu) {
        __syncthreads();
        for (int q = threadIdx.x; q < NCLS*NC; q += 256)
            atomicAdd(&g_clsum[q], ((float*)cls)[q]);
        if (threadIdx.x < 32)
            atomicAdd(&g_clcnt[lbls[threadIdx.x]], 1.f);
    }
}

// ---------------- K2: warp-MMA bf16 GEMM + exp2 + row-sum ----------------
// grid = 256 blocks: block b -> i-tile (b>>2), j-quarter (b&3); 2 blocks/SM
// co-resident so one block's ex2 (MUFU) burst overlaps the other's HMMA burst.
// Per j-tile: D[128,128] = S T^T (fp32 accum); bf16 rounding is zero-mean noise
// inside lse (measured cost ~1e-6 rel). Logits carry log2e -> bare ex2.
extern __shared__ char smem_raw[];

__global__ __launch_bounds__(256, 2) void k_main() {
    unsigned sbase = (unsigned)__cvta_generic_to_shared(smem_raw);
    int tid = threadIdx.x, lane = tid & 31, wid = tid >> 5;
    int i0    = (blockIdx.x >> 2) * BM;
    int jq    = blockIdx.x & 3;
    int jbase = jq * (NTOT / NQ);
    int wr = wid & 1, wc = wid >> 1;
    int m_base = wr * 64, n_base = wc * 32;
    int sub = lane >> 3, l7 = lane & 7;

    // ldmatrix per-lane address bases (layout validated in R8-R11 passes)
    unsigned a_rel[4]; int a_sw[4];
    #pragma unroll
    for (int mf = 0; mf < 4; mf++) {
        int row = m_base + mf * 16 + (sub & 1) * 8 + l7;
        a_rel[mf] = row * 256; a_sw[mf] = row & 7;
    }
    const int a_co = sub >> 1;
    unsigned b_rel[2]; int b_sw[2];
    #pragma unroll
    for (int p = 0; p < 2; p++) {
        int row = n_base + p * 16 + (sub >> 1) * 8 + l7;
        b_rel[p] = row * 256; b_sw[p] = row & 7;
    }
    const int b_co = sub & 1;

    // prologue: A resident + B tile 0
    load_tile(sbase + SM_A,  g_sh + (size_t)i0 * NC, tid);
    load_tile(sbase + SM_B0, g_th + (size_t)jbase * NC, tid);
    cpcommit();

    float rs[8];
    #pragma unroll
    for (int q = 0; q < 8; q++) rs[q] = 0.f;

    for (int jt = 0; jt < NT; jt++) {
        int b = jt & 1;
        cpwait<0>();
        __syncthreads();   // B(jt) visible; all warps done reading buf b^1

        if (jt + 1 < NT) { // prefetch B(jt+1) into the other buffer (overlaps MMA)
            int j0 = jbase + (jt + 1) * BN;
            load_tile(sbase + ((b ^ 1) ? SM_B1 : SM_B0), g_th + (size_t)j0 * NC, tid);
            cpcommit();
        }

        unsigned Ah = sbase + SM_A;
        unsigned Bh = sbase + (b ? SM_B1 : SM_B0);
        float c[4][4][4];
        #pragma unroll
        for (int mf = 0; mf < 4; mf++)
            #pragma unroll
            for (int nf = 0; nf < 4; nf++)
                #pragma unroll
                for (int q = 0; q < 4; q++) c[mf][nf][q] = 0.f;

        #pragma unroll
        for (int ks = 0; ks < 8; ks++) {
            unsigned ah[4][4], bh[2][4];
            #pragma unroll
            for (int mf = 0; mf < 4; mf++)
                ldsm4(ah[mf], Ah + a_rel[mf] + (((2*ks + a_co) ^ a_sw[mf]) << 4));
            #pragma unroll
            for (int p = 0; p < 2; p++)
                ldsm4(bh[p], Bh + b_rel[p] + (((2*ks + b_co) ^ b_sw[p]) << 4));
            #pragma unroll
            for (int mf = 0; mf < 4; mf++) {
                mma16816(c[mf][0], ah[mf], bh[0][0], bh[0][1]);
                mma16816(c[mf][1], ah[mf], bh[0][2], bh[0][3]);
                mma16816(c[mf][2], ah[mf], bh[1][0], bh[1][1]);
                mma16816(c[mf][3], ah[mf], bh[1][2], bh[1][3]);
            }
        }
        // 2^y accumulate (y = logit*log2e, |y|<=14.5 -> fp32 safe; no max pass)
        #pragma unroll
        for (int mf = 0; mf < 4; mf++) {
            float e0 = 0.f, e1 = 0.f;
            #pragma unroll
            for (int nf = 0; nf < 4; nf++) {
                e0 += ex2f(c[mf][nf][0]) + ex2f(c[mf][nf][1]);
                e1 += ex2f(c[mf][nf][2]) + ex2f(c[mf][nf][3]);
            }
            rs[mf*2]   += e0;   // row = m_base + mf*16 + lane/4
            rs[mf*2+1] += e1;   // row = m_base + mf*16 + lane/4 + 8
        }
    }

    __syncthreads();                      // SMEM reads done -> reuse as reduce space
    float* red = (float*)smem_raw;        // [128][4]
    #pragma unroll
    for (int q = 0; q < 8; q++) {
        rs[q] += __shfl_xor_sync(0xFFFFFFFFu, rs[q], 1);
        rs[q] += __shfl_xor_sync(0xFFFFFFFFu, rs[q], 2);
    }
    if ((lane & 3) == 0) {
        int r0 = m_base + (lane >> 2);
        #pragma unroll
        for (int mf = 0; mf < 4; mf++) {
            red[(r0 + mf*16    ) * 4 + wc] = rs[mf*2];
            red[(r0 + mf*16 + 8) * 4 + wc] = rs[mf*2+1];
        }
    }
    __syncthreads();
    if (tid < BM) {
        float s = red[tid*4] + red[tid*4+1] + red[tid*4+2] + red[tid*4+3];
        g_sep[jq * NTOT + i0 + tid] = s;   // single writer: deterministic
    }
}

// ---------------- K3: anchor terms from bf16 student (4 rows/warp) + loss ----------------
__global__ __launch_bounds__(256) void k_final(const void* sl, float* out) {
    int wid = threadIdx.x >> 5, lane = threadIdx.x & 31;
    int row0 = blockIdx.x * 32 + wid * 4;

    int lbl_own = 0;
    if (lane < 4) lbl_own = get_label(sl, row0 + lane);
    int lbl[4], lc[4];
    #pragma unroll
    for (int r = 0; r < 4; r++) {
        lbl[r] = __shfl_sync(0xFFFFFFFFu, lbl_own, r);
        lc[r] = min(max(lbl[r], 0), NCLS - 1);
    }

    float dot[4];
    #pragma unroll
    for (int r = 0; r < 4; r++) {
        // 4 bf16 student values (carry S_SCALE) + 4 fp32 clsum values per lane
        uint2 u = ((const uint2*)(g_sh + (size_t)(row0 + r) * NC))[lane];
        float4 b = ((const float4*)(g_clsum + lc[r] * NC))[lane];
        __nv_bfloat162 p0 = *(__nv_bfloat162*)&u.x;
        __nv_bfloat162 p1 = *(__nv_bfloat162*)&u.y;
        dot[r] = __bfloat162float(p0.x)*b.x + __bfloat162float(p0.y)*b.y
               + __bfloat162float(p1.x)*b.z + __bfloat162float(p1.y)*b.w;
    }
    #pragma unroll
    for (int r = 0; r < 4; r++)
        #pragma unroll
        for (int o = 16; o > 0; o >>= 1)
            dot[r] += __shfl_xor_sync(0xFFFFFFFFu, dot[r], o);

    __shared__ float r1s[8], r2s[8];
    if (lane == 0) {
        float s1 = 0.f, s2 = 0.f;
        #pragma unroll
        for (int r = 0; r < 4; r++) {
            int row = row0 + r;
            float cnt = g_clcnt[lc[r]];
            float lse = logf(g_sep[row] + g_sep[NTOT + row]
                           + g_sep[2*NTOT + row] + g_sep[3*NTOT + row]);
            float mlpp = (dot[r] * LN2 - cnt * lse) / (cnt + 1e-8f);
            float w = (cnt > 1e-8f && lbl[r] != 0) ? 1.f : 0.f;
            s1 += w * mlpp; s2 += w;
        }
        r1s[wid] = s1; r2s[wid] = s2;
    }
    __syncthreads();
    if (threadIdx.x == 0) {
        float s1 = 0.f, s2 = 0.f;
        #pragma unroll
        for (int q = 0; q < 8; q++) { s1 += r1s[q]; s2 += r2s[q]; }
        atomicAdd(&g_acc[0], s1);
        atomicAdd(&g_acc[1], s2);
        __threadfence();
        if (atomicAdd(&g_done, 1) == (int)gridDim.x - 1) {
            __threadfence();
            out[0] = -g_acc[0] / g_acc[1];
        }
    }
}

// ---------------- launch ----------------
extern "C" void kernel_launch(void* const* d_in, const int* in_sizes, int n_in,
                              void* d_out, int out_size) {
    const float* s_in = (const float*)d_in[0];
    const float* t_in = (const float*)d_in[1];
    const void*  sl   = d_in[2];
    const void*  tl   = d_in[3];
    float* out = (float*)d_out;

    cudaFuncSetAttribute(k_main, cudaFuncAttributeMaxDynamicSharedMemorySize, SMEM_TOTAL);

    k_init<<<1, 640>>>((const int*)sl, (const int*)tl);
    k_norm<<<dim3(256, 2), 256>>>(s_in, t_in, tl);
    k_main<<<(NTOT / BM) * NQ, 256, SMEM_TOTAL>>>();
    k_final<<<NTOT / 32, 256>>>(sl, out);
}

// round 13
// speedup vs baseline: 7.5395x; 1.0602x over previous
#include <cuda_runtime.h>
#include <cuda_bf16.h>
#include <math.h>

// Problem shape (fixed by dataset)
#define NB   8
#define NC   128
#define NHW  1024
#define NTOT (NB*NHW)      // 8192
#define NCLS 5
// student scale = (1/T) * log2(e): epilogue is bare ex2.approx
#define S_SCALE (10.0f * 1.4426950408889634f)
#define LN2 0.6931471805599453f

#define BM 128             // i-rows per block
#define BN 128             // j-cols per tile
#define NQ 16              // j-sixteenths: grid = 64 i-tiles * 16 = 1024 blocks
#define NT 4               // j-tiles per block

// dynamic smem (bytes): A shared + per-warp private B slice + reduce area
#define SM_A    0                      // 32768
#define SM_BW   32768                  // 8 warps x 8192 private slice
#define SM_RED  (32768 + 8*8192)       // 98304, 2048 bytes
#define SMEM_TOTAL (98304 + 2048)      // 100352 -> 2 blocks/SM

// ---------------- device scratch (no allocations allowed) ----------------
__device__ __nv_bfloat16 g_sh[NTOT*NC];   // student bf16 (*S_SCALE)
__device__ __nv_bfloat16 g_th[NTOT*NC];   // teacher bf16
__device__ float g_sep[NQ*NTOT];          // partial sum-of-exp (sixteenth, i); single writer
__device__ float g_clsum[NCLS*NC];
__device__ float g_clcnt[NCLS];
__device__ float g_acc[2];
__device__ int   g_done;
__device__ int   g_lmode;

// ---------------- helpers ----------------
__device__ __forceinline__ void cpasync16(unsigned smem, const void* g) {
    asm volatile("cp.async.cg.shared.global [%0], [%1], 16;\n" :: "r"(smem), "l"(g));
}
__device__ __forceinline__ void cpcommit() {
    asm volatile("cp.async.commit_group;\n" ::: "memory");
}
template<int N> __device__ __forceinline__ void cpwait() {
    asm volatile("cp.async.wait_group %0;\n" :: "n"(N) : "memory");
}
__device__ __forceinline__ int get_label(const void* p, int i) {
    if (g_lmode) return (int)(((const long long*)p)[i]);
    return ((const int*)p)[i];
}
__device__ __forceinline__ void ldsm4(unsigned* r, unsigned addr) {
    asm volatile("ldmatrix.sync.aligned.m8n8.x4.shared.b16 {%0,%1,%2,%3}, [%4];"
                 : "=r"(r[0]), "=r"(r[1]), "=r"(r[2]), "=r"(r[3]) : "r"(addr));
}
__device__ __forceinline__ void mma16816(float* c, const unsigned* a, unsigned b0, unsigned b1) {
    asm volatile("mma.sync.aligned.m16n8k16.row.col.f32.bf16.bf16.f32 "
                 "{%0,%1,%2,%3}, {%4,%5,%6,%7}, {%8,%9}, {%0,%1,%2,%3};"
                 : "+f"(c[0]), "+f"(c[1]), "+f"(c[2]), "+f"(c[3])
                 : "r"(a[0]), "r"(a[1]), "r"(a[2]), "r"(a[3]), "r"(b0), "r"(b1));
}
__device__ __forceinline__ float ex2f(float x) {
    float y; asm("ex2.approx.f32 %0, %1;" : "=f"(y) : "f"(x)); return y;
}

// Cooperative: one 128x128 bf16 tile into SMEM (swizzle c' = c ^ (row & 7)).
__device__ __forceinline__ void load_tile(unsigned dst, const __nv_bfloat16* src, int tid) {
    #pragma unroll
    for (int it = 0; it < 8; it++) {
        int idx = tid + it * 256;
        int row = idx >> 4, c = idx & 15;
        unsigned off = (unsigned)(row * 256 + ((c ^ (row & 7)) << 4));
        cpasync16(dst + off, (const char*)src + row * 256 + c * 16);
    }
}
// Per-warp: 32x128 bf16 slice (32 rows x 256B), same swizzle, 16 chunks/lane.
__device__ __forceinline__ void load_bslice(unsigned dst, const __nv_bfloat16* src, int lane) {
    #pragma unroll
    for (int it = 0; it < 16; it++) {
        int idx = lane + it * 32;
        int row = idx >> 4, c = idx & 15;
        unsigned off = (unsigned)(row * 256 + ((c ^ (row & 7)) << 4));
        cpasync16(dst + off, (const char*)src + row * 256 + c * 16);
    }
}

// ---------------- K0: label dtype probe + zero accumulators ----------------
__global__ void k_init(const int* sl, const int* tl) {
    int t = threadIdx.x;
    if (t == 0) {
        int allzero = 1;
        for (int i = 1; i < 256; i += 2)
            if (sl[i] != 0 || tl[i] != 0) { allzero = 0; break; }
        g_lmode = allzero;   // int64 labels 0..4 -> all odd 32-bit words zero
        g_done = 0;
    }
    if (t < NCLS*NC) g_clsum[t] = 0.f;
    if (t < NCLS)    g_clcnt[t] = 0.f;
    if (t < 2)       g_acc[t]   = 0.f;
}

// ---------------- K1: normalize + transpose + bf16 (+ teacher class sums) ----------------
__global__ __launch_bounds__(256) void k_norm(const float* __restrict__ s_in,
                                              const float* __restrict__ t_in,
                                              const void* __restrict__ tl) {
    __shared__ float sh[NC][33];
    __shared__ float part[8][32];
    __shared__ float invn[32];
    __shared__ float cls[NCLS][NC];
    __shared__ int lbls[32];
    int stu = (blockIdx.y == 0);
    const float* in   = stu ? s_in : t_in;
    __nv_bfloat16* outh = stu ? g_sh : g_th;
    const float scale = stu ? S_SCALE : 1.0f;
    int b   = blockIdx.x >> 5;
    int hw0 = (blockIdx.x & 31) << 5;
    int n0  = b * NHW + hw0;
    int tx = threadIdx.x & 31, ty = threadIdx.x >> 5;

    if (!stu) {
        for (int q = threadIdx.x; q < NCLS*NC; q += 256) ((float*)cls)[q] = 0.f;
        if (threadIdx.x < 32) {
            int l = get_label(tl, n0 + threadIdx.x);
            lbls[threadIdx.x] = min(max(l, 0), NCLS - 1);
        }
    }

    float p = 0.f;
    const float* base = in + (size_t)b * NC * NHW + hw0 + tx;
    #pragma unroll
    for (int c0 = 0; c0 < NC; c0 += 8) {
        float v = base[(size_t)(c0 + ty) * NHW];
        sh[c0 + ty][tx] = v;
        p += v * v;
    }
    part[ty][tx] = p;
    __syncthreads();
    if (ty == 0) {
        float s = 0.f;
        #pragma unroll
        for (int q = 0; q < 8; q++) s += part[q][tx];
        invn[tx] = rsqrtf(s) * scale;
    }
    __syncthreads();
    for (int idx = threadIdx.x; idx < NC * 32; idx += 256) {
        int c = idx & 127, q = idx >> 7;
        float v = sh[c][q] * invn[q];
        size_t o = (size_t)(n0 + q) * NC + c;
        outh[o] = __float2bfloat16(v);
        if (!stu) atomicAdd(&cls[lbls[q]][c], v);
    }
    if (!stu) {
        __syncthreads();
        for (int q = threadIdx.x; q < NCLS*NC; q += 256)
            atomicAdd(&g_clsum[q], ((float*)cls)[q]);
        if (threadIdx.x < 32)
            atomicAdd(&g_clcnt[lbls[threadIdx.x]], 1.f);
    }
}

// ---------------- K2: barrier-free warp-autonomous bf16 GEMM + exp2 ----------------
// grid = 1024 blocks: block b -> i-tile (b>>4), j-16th (b&15); occ 2 -> ~6.9
// small blocks/SM (near-ideal balance). Each warp owns a private B slice
// (its 32 n-cols) with its own cp.async groups: NO __syncthreads in the
// mainloop, so warps de-phase and ex2 (MUFU) overlaps HMMA across warps.
// Prefetch of tile jt+1 is issued before the ex2 burst -> latency hidden.
extern __shared__ char smem_raw[];

__global__ __launch_bounds__(256, 2) void k_main() {
    unsigned sbase = (unsigned)__cvta_generic_to_shared(smem_raw);
    int tid = threadIdx.x, lane = tid & 31, wid = tid >> 5;
    int i0    = (blockIdx.x >> 4) * BM;
    int jq    = blockIdx.x & 15;
    int jbase = jq * (NTOT / NQ);          // 512-wide j range
    int wr = wid & 1, wc = wid >> 1;
    int m_base = wr * 64, n_base = wc * 32;
    int sub = lane >> 3, l7 = lane & 7;
    unsigned mybuf = sbase + SM_BW + wid * 8192;

    // ldmatrix per-lane address bases (A shared tile; B local 32-row slice)
    unsigned a_rel[4]; int a_sw[4];
    #pragma unroll
    for (int mf = 0; mf < 4; mf++) {
        int row = m_base + mf * 16 + (sub & 1) * 8 + l7;
        a_rel[mf] = row * 256; a_sw[mf] = row & 7;
    }
    const int a_co = sub >> 1;
    unsigned b_rel[2]; int b_sw[2];
    #pragma unroll
    for (int p = 0; p < 2; p++) {
        int row = p * 16 + (sub >> 1) * 8 + l7;   // local row within slice
        b_rel[p] = row * 256; b_sw[p] = row & 7;
    }
    const int b_co = sub & 1;

    // prologue: A (cooperative) + own slice for tile 0, one group
    load_tile(sbase + SM_A, g_sh + (size_t)i0 * NC, tid);
    load_bslice(mybuf, g_th + (size_t)(jbase + n_base) * NC, lane);
    cpcommit();
    cpwait<0>();
    __syncthreads();      // A visible to all warps; only barrier before epilogue

    float rs[8];
    #pragma unroll
    for (int q = 0; q < 8; q++) rs[q] = 0.f;
    unsigned Ah = sbase + SM_A;

    #pragma unroll 1
    for (int jt = 0; jt < NT; jt++) {
        if (jt > 0) cpwait<0>();   // own prefetch done (latency hidden by prior ex2)

        float c[4][4][4];
        #pragma unroll
        for (int mf = 0; mf < 4; mf++)
            #pragma unroll
            for (int nf = 0; nf < 4; nf++)
                #pragma unroll
                for (int q = 0; q < 4; q++) c[mf][nf][q] = 0.f;

        #pragma unroll
        for (int ks = 0; ks < 8; ks++) {
            unsigned ah[4][4], bh[2][4];
            #pragma unroll
            for (int mf = 0; mf < 4; mf++)
                ldsm4(ah[mf], Ah + a_rel[mf] + (((2*ks + a_co) ^ a_sw[mf]) << 4));
            #pragma unroll
            for (int p = 0; p < 2; p++)
                ldsm4(bh[p], mybuf + b_rel[p] + (((2*ks + b_co) ^ b_sw[p]) << 4));
            #pragma unroll
            for (int mf = 0; mf < 4; mf++) {
                mma16816(c[mf][0], ah[mf], bh[0][0], bh[0][1]);
                mma16816(c[mf][1], ah[mf], bh[0][2], bh[0][3]);
                mma16816(c[mf][2], ah[mf], bh[1][0], bh[1][1]);
                mma16816(c[mf][3], ah[mf], bh[1][2], bh[1][3]);
            }
        }
        // prefetch next tile's slice NOW (all LDSMs for this tile already
        // executed; async writes land >=200cy later) -> covered by ex2 below
        if (jt + 1 < NT) {
            load_bslice(mybuf, g_th + (size_t)(jbase + (jt+1)*BN + n_base) * NC, lane);
            cpcommit();
        }
        // 2^y accumulate (y = logit*log2e, |y|<=14.5 -> fp32 safe; no max pass)
        #pragma unroll
        for (int mf = 0; mf < 4; mf++) {
            float e0 = 0.f, e1 = 0.f;
            #pragma unroll
            for (int nf = 0; nf < 4; nf++) {
                e0 += ex2f(c[mf][nf][0]) + ex2f(c[mf][nf][1]);
                e1 += ex2f(c[mf][nf][2]) + ex2f(c[mf][nf][3]);
            }
            rs[mf*2]   += e0;   // row = m_base + mf*16 + lane/4
            rs[mf*2+1] += e1;   // row = m_base + mf*16 + lane/4 + 8
        }
    }

    // epilogue reduction (separate SMEM region; one barrier)
    float* red = (float*)(smem_raw + SM_RED);   // [128][4]
    #pragma unroll
    for (int q = 0; q < 8; q++) {
        rs[q] += __shfl_xor_sync(0xFFFFFFFFu, rs[q], 1);
        rs[q] += __shfl_xor_sync(0xFFFFFFFFu, rs[q], 2);
    }
    if ((lane & 3) == 0) {
        int r0 = m_base + (lane >> 2);
        #pragma unroll
        for (int mf = 0; mf < 4; mf++) {
            red[(r0 + mf*16    ) * 4 + wc] = rs[mf*2];
            red[(r0 + mf*16 + 8) * 4 + wc] = rs[mf*2+1];
        }
    }
    __syncthreads();
    if (tid < BM) {
        float s = red[tid*4] + red[tid*4+1] + red[tid*4+2] + red[tid*4+3];
        g_sep[jq * NTOT + i0 + tid] = s;   // single writer: deterministic
    }
}

// ---------------- K3: anchor terms (8 rows/warp, MLP=8) + loss ----------------
__global__ __launch_bounds__(256) void k_final(const void* sl, float* out) {
    int wid = threadIdx.x >> 5, lane = threadIdx.x & 31;
    int row0 = blockIdx.x * 64 + wid * 8;

    int lbl_own = 0;
    if (lane < 8) lbl_own = get_label(sl, row0 + lane);
    int lbl[8], lc[8];
    #pragma unroll
    for (int r = 0; r < 8; r++) {
        lbl[r] = __shfl_sync(0xFFFFFFFFu, lbl_own, r);
        lc[r] = min(max(lbl[r], 0), NCLS - 1);
    }

    float dot[8];
    #pragma unroll
    for (int r = 0; r < 8; r++) {
        uint2 u = ((const uint2*)(g_sh + (size_t)(row0 + r) * NC))[lane];
        float4 b = ((const float4*)(g_clsum + lc[r] * NC))[lane];
        __nv_bfloat162 p0 = *(__nv_bfloat162*)&u.x;
        __nv_bfloat162 p1 = *(__nv_bfloat162*)&u.y;
        dot[r] = __bfloat162float(p0.x)*b.x + __bfloat162float(p0.y)*b.y
               + __bfloat162float(p1.x)*b.z + __bfloat162float(p1.y)*b.w;
    }
    #pragma unroll
    for (int r = 0; r < 8; r++)
        #pragma unroll
        for (int o = 16; o > 0; o >>= 1)
            dot[r] += __shfl_xor_sync(0xFFFFFFFFu, dot[r], o);

    // sum the 16 j-partials per row across lanes 0..15
    float sep[8];
    #pragma unroll
    for (int r = 0; r < 8; r++)
        sep[r] = (lane < NQ) ? g_sep[lane * NTOT + row0 + r] : 0.f;
    #pragma unroll
    for (int r = 0; r < 8; r++)
        #pragma unroll
        for (int o = 8; o > 0; o >>= 1)
            sep[r] += __shfl_xor_sync(0xFFFFFFFFu, sep[r], o);

    __shared__ float r1s[8], r2s[8];
    if (lane == 0) {
        float s1 = 0.f, s2 = 0.f;
        #pragma unroll
        for (int r = 0; r < 8; r++) {
            float cnt = g_clcnt[lc[r]];
            float lse = logf(sep[r]);
            float mlpp = (dot[r] * LN2 - cnt * lse) / (cnt + 1e-8f);
            float w = (cnt > 1e-8f && lbl[r] != 0) ? 1.f : 0.f;
            s1 += w * mlpp; s2 += w;
        }
        r1s[wid] = s1; r2s[wid] = s2;
    }
    __syncthreads();
    if (threadIdx.x == 0) {
        float s1 = 0.f, s2 = 0.f;
        #pragma unroll
        for (int q = 0; q < 8; q++) { s1 += r1s[q]; s2 += r2s[q]; }
        atomicAdd(&g_acc[0], s1);
        atomicAdd(&g_acc[1], s2);
        __threadfence();
        if (atomicAdd(&g_done, 1) == (int)gridDim.x - 1) {
            __threadfence();
            out[0] = -g_acc[0] / g_acc[1];
        }
    }
}

// ---------------- launch ----------------
extern "C" void kernel_launch(void* const* d_in, const int* in_sizes, int n_in,
                              void* d_out, int out_size) {
    const float* s_in = (const float*)d_in[0];
    const float* t_in = (const float*)d_in[1];
    const void*  sl   = d_in[2];
    const void*  tl   = d_in[3];
    float* out = (float*)d_out;

    cudaFuncSetAttribute(k_main, cudaFuncAttributeMaxDynamicSharedMemorySize, SMEM_TOTAL);

    k_init<<<1, 640>>>((const int*)sl, (const int*)tl);
    k_norm<<<dim3(256, 2), 256>>>(s_in, t_in, tl);
    k_main<<<(NTOT / BM) * NQ, 256, SMEM_TOTAL>>>();
    k_final<<<NTOT / 64, 256>>>(sl, out);
}